// round 12
// baseline (speedup 1.0000x reference)
#include <cuda_runtime.h>
#include <stdint.h>

#define NN 100000
#define NE 600000
#define D 128
#define SCAN_B 1024

#define SM_K 64
#define SM_PITCH 136
#define SLAB_WORDS (2 * SM_K * SM_PITCH)      // hi + lo planes, 17408 words
#define SM_BYTES (SLAB_WORDS * 4)             // 69632 B

// Scratch (device globals -- no runtime allocation allowed)
__device__ __align__(16) float g_msum[(size_t)NN * D];
__device__ __align__(16) float g_h1[(size_t)NN * D];
__device__ __align__(16) float g_h2[(size_t)NN * D];
__device__ __align__(16) uint32_t g_planes[8 * SLAB_WORDS];  // 4 mats x 2 khalves
__device__ int g_cnt[NN];
__device__ int g_fill[NN];
__device__ int g_rowptr[NN + 1];
__device__ int g_col[NE];
__device__ int g_blocksum[128];
__device__ int g_blockoff[128];
__device__ int g_is64;

// ---------------------------------------------------------------------------
// Packed f32x2 helpers (for the SIMT lin kernels)
// ---------------------------------------------------------------------------
__device__ __forceinline__ void ffma2(unsigned long long& acc,
                                      unsigned long long a,
                                      unsigned long long b) {
    asm("fma.rn.f32x2 %0, %1, %2, %0;" : "+l"(acc) : "l"(a), "l"(b));
}
__device__ __forceinline__ unsigned long long pack2(float lo, float hi) {
    unsigned long long r;
    asm("mov.b64 %0, {%1, %2};" : "=l"(r) : "f"(lo), "f"(hi));
    return r;
}
__device__ __forceinline__ float2 unpack2(unsigned long long v) {
    float lo, hi;
    asm("mov.b64 {%0, %1}, %2;" : "=f"(lo), "=f"(hi) : "l"(v));
    return make_float2(lo, hi);
}

// ---------------------------------------------------------------------------
// tf32 helpers
// ---------------------------------------------------------------------------
__device__ __forceinline__ uint32_t f2tf32(float f) {
    uint32_t r;
    asm("cvt.rna.tf32.f32 %0, %1;" : "=r"(r) : "f"(f));
    return r;
}
__device__ __forceinline__ void mma_tf32(float& c0, float& c1, float& c2,
                                         float& c3, uint32_t a0, uint32_t a1,
                                         uint32_t a2, uint32_t a3, uint32_t b0,
                                         uint32_t b1) {
    asm("mma.sync.aligned.m16n8k8.row.col.f32.tf32.tf32.f32 "
        "{%0,%1,%2,%3},{%4,%5,%6,%7},{%8,%9},{%0,%1,%2,%3};"
        : "+f"(c0), "+f"(c1), "+f"(c2), "+f"(c3)
        : "r"(a0), "r"(a1), "r"(a2), "r"(a3), "r"(b0), "r"(b1));
}

__device__ __forceinline__ int edge_at(const void* __restrict__ ei, int i) {
    if (g_is64) return (int)((const long long*)ei)[i];
    return ((const int*)ei)[i];
}

// ---------------------------------------------------------------------------
// init: zero cnt/fill arrays; block 0 also sniffs edge-index dtype
// (reference says int64; default JAX yields int32)
// ---------------------------------------------------------------------------
__global__ void init_kernel(const unsigned int* __restrict__ ei32, int npairs,
                            int n) {
    int i = blockIdx.x * blockDim.x + threadIdx.x;
    if (i < n) { g_cnt[i] = 0; g_fill[i] = 0; }
    if (blockIdx.x == 0) {
        __shared__ int any;
        if (threadIdx.x == 0) any = 0;
        __syncthreads();
        int found = 0;
        for (int j = threadIdx.x; j < npairs; j += blockDim.x)
            if (ei32[2 * j + 1] != 0u) found = 1;
        if (found) any = 1;   // benign race
        __syncthreads();
        if (threadIdx.x == 0) g_is64 = (any == 0);
    }
}

// ---------------------------------------------------------------------------
// Precompute tf32 hi/lo weight planes, laid out exactly as the SMEM slabs.
// Slab s = mat*2 + khalf; within a slab: hi plane then lo plane.
// mat: 0=s0Wl, 1=s0Wr, 2=s1Wl, 3=s1Wr.
// ---------------------------------------------------------------------------
__global__ void prep_planes_kernel(const float* __restrict__ Wl0,
                                   const float* __restrict__ Wr0,
                                   const float* __restrict__ Wl1,
                                   const float* __restrict__ Wr1) {
    int idx = blockIdx.x * blockDim.x + threadIdx.x;
    if (idx >= 4 * D * D) return;
    int mat = idx >> 14;
    int e = idx & 16383;
    int k = e >> 7, nn = e & 127;
    const float* W = (mat == 0) ? Wl0 : (mat == 1) ? Wr0 : (mat == 2) ? Wl1 : Wr1;
    float w = W[k * D + nn];
    uint32_t hi = f2tf32(w);
    uint32_t lo = f2tf32(w - __uint_as_float(hi));
    int khalf = k >> 6, kk = k & 63;
    uint32_t* slab = g_planes + (mat * 2 + khalf) * SLAB_WORDS;
    slab[kk * SM_PITCH + nn] = hi;
    slab[SM_K * SM_PITCH + kk * SM_PITCH + nn] = lo;
}

// ---------------------------------------------------------------------------
// CSR build: histogram -> block scan -> fill
// ---------------------------------------------------------------------------
__global__ void hist_kernel(const void* __restrict__ ei, int E, int n) {
    int e = blockIdx.x * blockDim.x + threadIdx.x;
    if (e >= E) return;
    unsigned d = min((unsigned)edge_at(ei, E + e), (unsigned)(n - 1));
    atomicAdd(&g_cnt[d], 1);
}

__global__ void __launch_bounds__(SCAN_B) scan1_kernel(int n) {
    __shared__ int sm[SCAN_B];
    int i = blockIdx.x * SCAN_B + threadIdx.x;
    sm[threadIdx.x] = (i < n) ? g_cnt[i] : 0;
    __syncthreads();
    for (int off = SCAN_B / 2; off > 0; off >>= 1) {
        if (threadIdx.x < off) sm[threadIdx.x] += sm[threadIdx.x + off];
        __syncthreads();
    }
    if (threadIdx.x == 0) g_blocksum[blockIdx.x] = sm[0];
}

__global__ void scan2_kernel(int nb, int n, int E) {
    if (threadIdx.x == 0) {
        int run = 0;
        for (int b = 0; b < nb; b++) { g_blockoff[b] = run; run += g_blocksum[b]; }
        g_rowptr[n] = E;
    }
}

__global__ void __launch_bounds__(SCAN_B) scan3_kernel(int n) {
    __shared__ int sm[SCAN_B];
    int i = blockIdx.x * SCAN_B + threadIdx.x;
    int v = (i < n) ? g_cnt[i] : 0;
    sm[threadIdx.x] = v;
    __syncthreads();
    for (int off = 1; off < SCAN_B; off <<= 1) {
        int t = 0;
        if ((int)threadIdx.x >= off) t = sm[threadIdx.x - off];
        __syncthreads();
        if ((int)threadIdx.x >= off) sm[threadIdx.x] += t;
        __syncthreads();
    }
    if (i < n) g_rowptr[i] = g_blockoff[blockIdx.x] + sm[threadIdx.x] - v;
}

__global__ void fill_kernel(const void* __restrict__ ei, int E, int n) {
    int e = blockIdx.x * blockDim.x + threadIdx.x;
    if (e >= E) return;
    unsigned s = min((unsigned)edge_at(ei, e), (unsigned)(n - 1));
    unsigned d = min((unsigned)edge_at(ei, E + e), (unsigned)(n - 1));
    int pos = g_rowptr[d] + atomicAdd(&g_fill[d], 1);
    g_col[pos] = (int)s;
}

// ---------------------------------------------------------------------------
// SAGE layer via tensor cores (3xTF32) with FUSED mean-aggregation prologue.
// Block = 8 warps x 16 nodes = 128 nodes. Each warp first gathers the mean
// of in-neighbors for its own 16 rows (writes g_msum; rows stay L1/L2-hot),
// then the block runs the GEMM: out = relu(msum@Wl + bl + h@Wr).
// Weight slabs (precomputed hi/lo tf32 planes) are flat-copied to SMEM.
// LAYER selects weights slab set; SRC/OUT select activation buffers.
// ---------------------------------------------------------------------------
template <int LAYER, int SRC, int OUT>
__global__ void __launch_bounds__(256, 2) sage_mma(
    const float* __restrict__ x, const float* __restrict__ bl, int n) {
    extern __shared__ uint32_t sw[];
    uint32_t* sWhi = sw;
    uint32_t* sWlo = sw + SM_K * SM_PITCH;

    const int tid = threadIdx.x;
    const int wid = tid >> 5;
    const int lane = tid & 31;
    const int g = lane >> 2;     // group id: row within tile
    const int tig = lane & 3;    // thread in group: k / col selector

    const float* h = (SRC == 0) ? x : g_h1;
    float* out = (OUT == 1) ? g_h1 : g_h2;

    const int wbase = blockIdx.x * 128 + wid * 16;

    // ---- fused aggregation: this warp's 16 rows ----
#pragma unroll 1
    for (int j = 0; j < 16; ++j) {
        int node = wbase + j;
        int nodeC = min(node, n - 1);
        int beg = g_rowptr[nodeC], end = g_rowptr[nodeC + 1];
        float4 acc = make_float4(0.f, 0.f, 0.f, 0.f);
        int k = beg;
        for (; k + 4 <= end; k += 4) {
            int c0 = g_col[k + 0], c1 = g_col[k + 1];
            int c2 = g_col[k + 2], c3 = g_col[k + 3];
            float4 v0 = *(const float4*)(h + (size_t)c0 * D + lane * 4);
            float4 v1 = *(const float4*)(h + (size_t)c1 * D + lane * 4);
            float4 v2 = *(const float4*)(h + (size_t)c2 * D + lane * 4);
            float4 v3 = *(const float4*)(h + (size_t)c3 * D + lane * 4);
            acc.x += v0.x + v1.x + v2.x + v3.x;
            acc.y += v0.y + v1.y + v2.y + v3.y;
            acc.z += v0.z + v1.z + v2.z + v3.z;
            acc.w += v0.w + v1.w + v2.w + v3.w;
        }
        for (; k < end; ++k) {
            int c = g_col[k];
            float4 v = *(const float4*)(h + (size_t)c * D + lane * 4);
            acc.x += v.x; acc.y += v.y; acc.z += v.z; acc.w += v.w;
        }
        float sc = 1.f / fmaxf((float)(end - beg), 1.f);
        acc.x *= sc; acc.y *= sc; acc.z *= sc; acc.w *= sc;
        if (node < n)
            *(float4*)(g_msum + (size_t)node * D + lane * 4) = acc;
    }

    const int r0 = min(wbase + g, n - 1);
    const int r1 = min(wbase + g + 8, n - 1);

    // C fragments: 16 n-tiles x 4 regs, initialized with bias
    float c[16][4];
#pragma unroll
    for (int nt = 0; nt < 16; ++nt) {
        int col0 = nt * 8 + tig * 2;
        float b0 = bl[col0], b1 = bl[col0 + 1];
        c[nt][0] = b0; c[nt][1] = b1;
        c[nt][2] = b0; c[nt][3] = b1;
    }

#pragma unroll 1
    for (int pass = 0; pass < 4; ++pass) {
        // slab: mat = LAYER*2 + (0 for Wl, 1 for Wr); khalf = pass&1
        const int mat = LAYER * 2 + ((pass < 2) ? 0 : 1);
        const uint32_t* slab = g_planes + (mat * 2 + (pass & 1)) * SLAB_WORDS;
        const float* A = (pass < 2) ? g_msum : h;
        const int k0 = (pass & 1) * SM_K;

        __syncthreads();
        // flat copy of precomputed hi+lo planes (17408 words = 4352 float4)
        {
            const float4* src4 = (const float4*)slab;
            float4* dst4 = (float4*)sw;
            for (int idx = tid; idx < SLAB_WORDS / 4; idx += 256)
                dst4[idx] = src4[idx];
        }
        __syncthreads();

        const float* a0p = A + (size_t)r0 * D + k0;
        const float* a1p = A + (size_t)r1 * D + k0;

#pragma unroll
        for (int ks = 0; ks < 8; ++ks) {
            const int kc = ks * 8 + tig;
            float f0 = a0p[kc], f1 = a1p[kc];
            float f2v = a0p[kc + 4], f3 = a1p[kc + 4];
            uint32_t ah0 = f2tf32(f0), ah1 = f2tf32(f1);
            uint32_t ah2 = f2tf32(f2v), ah3 = f2tf32(f3);
            uint32_t al0 = f2tf32(f0 - __uint_as_float(ah0));
            uint32_t al1 = f2tf32(f1 - __uint_as_float(ah1));
            uint32_t al2 = f2tf32(f2v - __uint_as_float(ah2));
            uint32_t al3 = f2tf32(f3 - __uint_as_float(ah3));

            const int kb = (ks * 8 + tig) * SM_PITCH + g;
#pragma unroll
            for (int nt = 0; nt < 16; ++nt) {
                const int base = kb + nt * 8;
                uint32_t bh0 = sWhi[base];
                uint32_t bh1 = sWhi[base + 4 * SM_PITCH];
                uint32_t bl0 = sWlo[base];
                uint32_t bl1 = sWlo[base + 4 * SM_PITCH];
                mma_tf32(c[nt][0], c[nt][1], c[nt][2], c[nt][3],
                         ah0, ah1, ah2, ah3, bh0, bh1);
                mma_tf32(c[nt][0], c[nt][1], c[nt][2], c[nt][3],
                         ah0, ah1, ah2, ah3, bl0, bl1);
                mma_tf32(c[nt][0], c[nt][1], c[nt][2], c[nt][3],
                         al0, al1, al2, al3, bh0, bh1);
            }
        }
    }

    // epilogue: relu + store (rows g and g+8)
    const int row0 = wbase + g;
    const int row1 = wbase + g + 8;
    if (row0 < n) {
        float* o = out + (size_t)row0 * D + tig * 2;
#pragma unroll
        for (int nt = 0; nt < 16; ++nt)
            *(float2*)(o + nt * 8) =
                make_float2(fmaxf(c[nt][0], 0.f), fmaxf(c[nt][1], 0.f));
    }
    if (row1 < n) {
        float* o = out + (size_t)row1 * D + tig * 2;
#pragma unroll
        for (int nt = 0; nt < 16; ++nt)
            *(float2*)(o + nt * 8) =
                make_float2(fmaxf(c[nt][2], 0.f), fmaxf(c[nt][3], 0.f));
    }
}

// ---------------------------------------------------------------------------
// lin0: t = relu(g_h2 @ W0 + b0) -> g_msum[node*64 + col]  (SIMT FFMA2)
// ---------------------------------------------------------------------------
__global__ void __launch_bounds__(256) lin0_kernel(
    const float* __restrict__ W0, const float* __restrict__ b0, int n) {
    __shared__ float sW0[D * 32];
    __shared__ float sb[32];

    const int j0 = blockIdx.y * 32;
    for (int idx = threadIdx.x; idx < D * 32; idx += 256) {
        int k = idx >> 5, jj = idx & 31;
        sW0[idx] = W0[k * 64 + j0 + jj];
    }
    if (threadIdx.x < 32) sb[threadIdx.x] = b0[j0 + threadIdx.x];
    __syncthreads();

    int nd[4];
    const float4* hp[4];
#pragma unroll
    for (int i = 0; i < 4; i++) {
        nd[i] = blockIdx.x * 1024 + threadIdx.x + i * 256;
        int c = min(nd[i], n - 1);
        hp[i] = (const float4*)(g_h2 + (size_t)c * D);
    }

    unsigned long long acc[4][16];
#pragma unroll
    for (int p = 0; p < 16; p++) {
        unsigned long long b = pack2(sb[2 * p], sb[2 * p + 1]);
#pragma unroll
        for (int i = 0; i < 4; i++) acc[i][p] = b;
    }

    for (int k4 = 0; k4 < 32; ++k4) {
        float ar[4][4];
#pragma unroll
        for (int i = 0; i < 4; i++) {
            float4 q = hp[i][k4];
            ar[i][0] = q.x; ar[i][1] = q.y; ar[i][2] = q.z; ar[i][3] = q.w;
        }
#pragma unroll
        for (int kk = 0; kk < 4; ++kk) {
            const int kbase = (k4 * 4 + kk) * 32;
            ulonglong2 w0 = *(const ulonglong2*)&sW0[kbase + 0];
            ulonglong2 w1 = *(const ulonglong2*)&sW0[kbase + 4];
            ulonglong2 w2 = *(const ulonglong2*)&sW0[kbase + 8];
            ulonglong2 w3 = *(const ulonglong2*)&sW0[kbase + 12];
            ulonglong2 w4 = *(const ulonglong2*)&sW0[kbase + 16];
            ulonglong2 w5 = *(const ulonglong2*)&sW0[kbase + 20];
            ulonglong2 w6 = *(const ulonglong2*)&sW0[kbase + 24];
            ulonglong2 w7 = *(const ulonglong2*)&sW0[kbase + 28];
#pragma unroll
            for (int i = 0; i < 4; i++) {
                unsigned long long pr = pack2(ar[i][kk], ar[i][kk]);
                ffma2(acc[i][0],  pr, w0.x);
                ffma2(acc[i][1],  pr, w0.y);
                ffma2(acc[i][2],  pr, w1.x);
                ffma2(acc[i][3],  pr, w1.y);
                ffma2(acc[i][4],  pr, w2.x);
                ffma2(acc[i][5],  pr, w2.y);
                ffma2(acc[i][6],  pr, w3.x);
                ffma2(acc[i][7],  pr, w3.y);
                ffma2(acc[i][8],  pr, w4.x);
                ffma2(acc[i][9],  pr, w4.y);
                ffma2(acc[i][10], pr, w5.x);
                ffma2(acc[i][11], pr, w5.y);
                ffma2(acc[i][12], pr, w6.x);
                ffma2(acc[i][13], pr, w6.y);
                ffma2(acc[i][14], pr, w7.x);
                ffma2(acc[i][15], pr, w7.y);
            }
        }
    }

#pragma unroll
    for (int i = 0; i < 4; i++) {
        if (nd[i] < n) {
            float4* o = (float4*)(g_msum + (size_t)nd[i] * 64 + j0);
#pragma unroll
            for (int q = 0; q < 8; ++q) {
                float2 a = unpack2(acc[i][q * 2 + 0]);
                float2 b = unpack2(acc[i][q * 2 + 1]);
                o[q] = make_float4(fmaxf(a.x, 0.f), fmaxf(a.y, 0.f),
                                   fmaxf(b.x, 0.f), fmaxf(b.y, 0.f));
            }
        }
    }
}

// ---------------------------------------------------------------------------
// lin1: out = relu(t @ W1 + b1), t = g_msum[node*64 .. +64]
// ---------------------------------------------------------------------------
__global__ void __launch_bounds__(256) lin1_kernel(
    const float* __restrict__ W1, const float* __restrict__ b1,
    float* __restrict__ out, int n) {
    __shared__ float sW1[64 * 8];
    __shared__ float sb1[8];
    for (int idx = threadIdx.x; idx < 64 * 8; idx += 256) sW1[idx] = W1[idx];
    if (threadIdx.x < 8) sb1[threadIdx.x] = b1[threadIdx.x];
    __syncthreads();

    const int n0 = blockIdx.x * 256 + threadIdx.x;
    const int c0 = min(n0, n - 1);
    const float4* tp = (const float4*)(g_msum + (size_t)c0 * 64);

    unsigned long long o2[4];
#pragma unroll
    for (int p = 0; p < 4; p++) o2[p] = pack2(sb1[2 * p], sb1[2 * p + 1]);

#pragma unroll
    for (int k4 = 0; k4 < 16; ++k4) {
        float4 tv = tp[k4];
        float r[4] = {tv.x, tv.y, tv.z, tv.w};
#pragma unroll
        for (int kk = 0; kk < 4; ++kk) {
            const int kbase = (k4 * 4 + kk) * 8;
            ulonglong2 wA = *(const ulonglong2*)&sW1[kbase + 0];
            ulonglong2 wB = *(const ulonglong2*)&sW1[kbase + 4];
            unsigned long long pr = pack2(r[kk], r[kk]);
            ffma2(o2[0], pr, wA.x);
            ffma2(o2[1], pr, wA.y);
            ffma2(o2[2], pr, wB.x);
            ffma2(o2[3], pr, wB.y);
        }
    }

    if (n0 < n) {
        float4* op = (float4*)(out + (size_t)n0 * 8);
        float2 a = unpack2(o2[0]), b = unpack2(o2[1]);
        float2 c = unpack2(o2[2]), dd = unpack2(o2[3]);
        op[0] = make_float4(fmaxf(a.x, 0.f), fmaxf(a.y, 0.f),
                            fmaxf(b.x, 0.f), fmaxf(b.y, 0.f));
        op[1] = make_float4(fmaxf(c.x, 0.f), fmaxf(c.y, 0.f),
                            fmaxf(dd.x, 0.f), fmaxf(dd.y, 0.f));
    }
}

// ---------------------------------------------------------------------------
// Launcher (no allocation, graph-capturable)
// ---------------------------------------------------------------------------
extern "C" void kernel_launch(void* const* d_in, const int* in_sizes, int n_in,
                              void* d_out, int out_size) {
    const float* x    = (const float*)d_in[0];
    const void*  ei   = d_in[1];
    const float* s0Wl = (const float*)d_in[2];
    const float* s0bl = (const float*)d_in[3];
    const float* s0Wr = (const float*)d_in[4];
    const float* s1Wl = (const float*)d_in[5];
    const float* s1bl = (const float*)d_in[6];
    const float* s1Wr = (const float*)d_in[7];
    const float* l0W  = (const float*)d_in[8];
    const float* l0b  = (const float*)d_in[9];
    const float* l1W  = (const float*)d_in[10];
    const float* l1b  = (const float*)d_in[11];
    float* out = (float*)d_out;

    const int N = in_sizes[0] / D;
    const int E = in_sizes[1] / 2;
    const int NB = (N + SCAN_B - 1) / SCAN_B;

    cudaFuncSetAttribute(sage_mma<0, 0, 1>,
                         cudaFuncAttributeMaxDynamicSharedMemorySize, SM_BYTES);
    cudaFuncSetAttribute(sage_mma<1, 1, 2>,
                         cudaFuncAttributeMaxDynamicSharedMemorySize, SM_BYTES);

    // init (zero + dtype sniff) and weight-plane precompute
    init_kernel<<<(N + 255) / 256, 256>>>((const unsigned int*)ei, 2048, N);
    prep_planes_kernel<<<(4 * D * D + 255) / 256, 256>>>(s0Wl, s0Wr, s1Wl,
                                                         s1Wr);

    // CSR build (once per launch; shared by both layers)
    hist_kernel<<<(E + 255) / 256, 256>>>(ei, E, N);
    scan1_kernel<<<NB, SCAN_B>>>(N);
    scan2_kernel<<<1, 32>>>(NB, N, E);
    scan3_kernel<<<NB, SCAN_B>>>(N);
    fill_kernel<<<(E + 255) / 256, 256>>>(ei, E, N);

    const int mma_blocks = (N + 127) / 128;
    dim3 lgrid((N + 1023) / 1024, 2);

    // layer 0 (fused agg + GEMM)
    sage_mma<0, 0, 1><<<mma_blocks, 256, SM_BYTES>>>(x, s0bl, N);

    // layer 1 (fused agg + GEMM)
    sage_mma<1, 1, 2><<<mma_blocks, 256, SM_BYTES>>>(x, s1bl, N);

    // MLP head
    lin0_kernel<<<lgrid, 256>>>(l0W, l0b, N);
    lin1_kernel<<<(N + 255) / 256, 256>>>(l1W, l1b, out, N);
}

// round 13
// speedup vs baseline: 1.0986x; 1.0986x over previous
#include <cuda_runtime.h>
#include <stdint.h>

#define NN 100000
#define NE 600000
#define D 128
#define SCAN_B 1024

#define SM_K 64
#define SM_PITCH 136
#define SLAB_WORDS (2 * SM_K * SM_PITCH)      // hi + lo planes, 17408 words
#define SM_BYTES (SLAB_WORDS * 4)             // 69632 B

// Scratch (device globals -- no runtime allocation allowed)
__device__ __align__(16) float g_msum[(size_t)NN * D];
__device__ __align__(16) float g_h1[(size_t)NN * D];
__device__ __align__(16) float g_h2[(size_t)NN * D];
__device__ __align__(16) uint32_t g_planes[8 * SLAB_WORDS];  // 4 mats x 2 khalves
__device__ int g_cnt[NN];
__device__ int g_fill[NN];
__device__ int g_rowptr[NN + 1];
__device__ int g_col[NE];
__device__ int g_blocksum[128];
__device__ int g_blockoff[128];
__device__ int g_is64;

// ---------------------------------------------------------------------------
// Packed f32x2 helpers (for the SIMT lin kernels)
// ---------------------------------------------------------------------------
__device__ __forceinline__ void ffma2(unsigned long long& acc,
                                      unsigned long long a,
                                      unsigned long long b) {
    asm("fma.rn.f32x2 %0, %1, %2, %0;" : "+l"(acc) : "l"(a), "l"(b));
}
__device__ __forceinline__ unsigned long long pack2(float lo, float hi) {
    unsigned long long r;
    asm("mov.b64 %0, {%1, %2};" : "=l"(r) : "f"(lo), "f"(hi));
    return r;
}
__device__ __forceinline__ float2 unpack2(unsigned long long v) {
    float lo, hi;
    asm("mov.b64 {%0, %1}, %2;" : "=f"(lo), "=f"(hi) : "l"(v));
    return make_float2(lo, hi);
}

// ---------------------------------------------------------------------------
// tf32 helpers
// ---------------------------------------------------------------------------
__device__ __forceinline__ uint32_t f2tf32(float f) {
    uint32_t r;
    asm("cvt.rna.tf32.f32 %0, %1;" : "=r"(r) : "f"(f));
    return r;
}
__device__ __forceinline__ void mma_tf32(float& c0, float& c1, float& c2,
                                         float& c3, uint32_t a0, uint32_t a1,
                                         uint32_t a2, uint32_t a3, uint32_t b0,
                                         uint32_t b1) {
    asm("mma.sync.aligned.m16n8k8.row.col.f32.tf32.tf32.f32 "
        "{%0,%1,%2,%3},{%4,%5,%6,%7},{%8,%9},{%0,%1,%2,%3};"
        : "+f"(c0), "+f"(c1), "+f"(c2), "+f"(c3)
        : "r"(a0), "r"(a1), "r"(a2), "r"(a3), "r"(b0), "r"(b1));
}

__device__ __forceinline__ int edge_at(const void* __restrict__ ei, int i) {
    if (g_is64) return (int)((const long long*)ei)[i];
    return ((const int*)ei)[i];
}

// ---------------------------------------------------------------------------
// init: zero cnt/fill arrays; block 0 also sniffs edge-index dtype
// (reference says int64; default JAX yields int32)
// ---------------------------------------------------------------------------
__global__ void init_kernel(const unsigned int* __restrict__ ei32, int npairs,
                            int n) {
    int i = blockIdx.x * blockDim.x + threadIdx.x;
    if (i < n) { g_cnt[i] = 0; g_fill[i] = 0; }
    if (blockIdx.x == 0) {
        __shared__ int any;
        if (threadIdx.x == 0) any = 0;
        __syncthreads();
        int found = 0;
        for (int j = threadIdx.x; j < npairs; j += blockDim.x)
            if (ei32[2 * j + 1] != 0u) found = 1;
        if (found) any = 1;   // benign race
        __syncthreads();
        if (threadIdx.x == 0) g_is64 = (any == 0);
    }
}

// ---------------------------------------------------------------------------
// Precompute tf32 hi/lo weight planes, laid out exactly as the SMEM slabs.
// Slab s = mat*2 + khalf; within a slab: hi plane then lo plane.
// mat: 0=s0Wl, 1=s0Wr, 2=s1Wl, 3=s1Wr.
// ---------------------------------------------------------------------------
__global__ void prep_planes_kernel(const float* __restrict__ Wl0,
                                   const float* __restrict__ Wr0,
                                   const float* __restrict__ Wl1,
                                   const float* __restrict__ Wr1) {
    int idx = blockIdx.x * blockDim.x + threadIdx.x;
    if (idx >= 4 * D * D) return;
    int mat = idx >> 14;
    int e = idx & 16383;
    int k = e >> 7, nn = e & 127;
    const float* W = (mat == 0) ? Wl0 : (mat == 1) ? Wr0 : (mat == 2) ? Wl1 : Wr1;
    float w = W[k * D + nn];
    uint32_t hi = f2tf32(w);
    uint32_t lo = f2tf32(w - __uint_as_float(hi));
    int khalf = k >> 6, kk = k & 63;
    uint32_t* slab = g_planes + (mat * 2 + khalf) * SLAB_WORDS;
    slab[kk * SM_PITCH + nn] = hi;
    slab[SM_K * SM_PITCH + kk * SM_PITCH + nn] = lo;
}

// ---------------------------------------------------------------------------
// CSR build: histogram -> block scan -> fill
// ---------------------------------------------------------------------------
__global__ void hist_kernel(const void* __restrict__ ei, int E, int n) {
    int e = blockIdx.x * blockDim.x + threadIdx.x;
    if (e >= E) return;
    unsigned d = min((unsigned)edge_at(ei, E + e), (unsigned)(n - 1));
    atomicAdd(&g_cnt[d], 1);
}

__global__ void __launch_bounds__(SCAN_B) scan1_kernel(int n) {
    __shared__ int sm[SCAN_B];
    int i = blockIdx.x * SCAN_B + threadIdx.x;
    sm[threadIdx.x] = (i < n) ? g_cnt[i] : 0;
    __syncthreads();
    for (int off = SCAN_B / 2; off > 0; off >>= 1) {
        if (threadIdx.x < off) sm[threadIdx.x] += sm[threadIdx.x + off];
        __syncthreads();
    }
    if (threadIdx.x == 0) g_blocksum[blockIdx.x] = sm[0];
}

__global__ void scan2_kernel(int nb, int n, int E) {
    if (threadIdx.x == 0) {
        int run = 0;
        for (int b = 0; b < nb; b++) { g_blockoff[b] = run; run += g_blocksum[b]; }
        g_rowptr[n] = E;
    }
}

__global__ void __launch_bounds__(SCAN_B) scan3_kernel(int n) {
    __shared__ int sm[SCAN_B];
    int i = blockIdx.x * SCAN_B + threadIdx.x;
    int v = (i < n) ? g_cnt[i] : 0;
    sm[threadIdx.x] = v;
    __syncthreads();
    for (int off = 1; off < SCAN_B; off <<= 1) {
        int t = 0;
        if ((int)threadIdx.x >= off) t = sm[threadIdx.x - off];
        __syncthreads();
        if ((int)threadIdx.x >= off) sm[threadIdx.x] += t;
        __syncthreads();
    }
    if (i < n) g_rowptr[i] = g_blockoff[blockIdx.x] + sm[threadIdx.x] - v;
}

__global__ void fill_kernel(const void* __restrict__ ei, int E, int n) {
    int e = blockIdx.x * blockDim.x + threadIdx.x;
    if (e >= E) return;
    unsigned s = min((unsigned)edge_at(ei, e), (unsigned)(n - 1));
    unsigned d = min((unsigned)edge_at(ei, E + e), (unsigned)(n - 1));
    int pos = g_rowptr[d] + atomicAdd(&g_fill[d], 1);
    g_col[pos] = (int)s;
}

// ---------------------------------------------------------------------------
// Gather aggregation: msum[i] = mean over in-neighbors of h[col].
// One warp per node; lane owns 16B. 4-deep unroll for MLP. (Standalone:
// full-grid launch gives the gather the occupancy it needs to hide latency.)
// ---------------------------------------------------------------------------
template <int SRC>
__global__ void __launch_bounds__(256) agg_kernel(const float* __restrict__ x,
                                                  int n) {
    int tid = blockIdx.x * blockDim.x + threadIdx.x;
    int node = tid >> 5;
    if (node >= n) return;
    int lane = tid & 31;
    const float* h = (SRC == 0) ? x : g_h1;
    int beg = g_rowptr[node], end = g_rowptr[node + 1];
    float4 acc = make_float4(0.f, 0.f, 0.f, 0.f);
    int k = beg;
    for (; k + 4 <= end; k += 4) {
        int c0 = g_col[k + 0], c1 = g_col[k + 1];
        int c2 = g_col[k + 2], c3 = g_col[k + 3];
        float4 v0 = *(const float4*)(h + (size_t)c0 * D + lane * 4);
        float4 v1 = *(const float4*)(h + (size_t)c1 * D + lane * 4);
        float4 v2 = *(const float4*)(h + (size_t)c2 * D + lane * 4);
        float4 v3 = *(const float4*)(h + (size_t)c3 * D + lane * 4);
        acc.x += v0.x + v1.x + v2.x + v3.x;
        acc.y += v0.y + v1.y + v2.y + v3.y;
        acc.z += v0.z + v1.z + v2.z + v3.z;
        acc.w += v0.w + v1.w + v2.w + v3.w;
    }
    for (; k < end; ++k) {
        int c = g_col[k];
        float4 v = *(const float4*)(h + (size_t)c * D + lane * 4);
        acc.x += v.x; acc.y += v.y; acc.z += v.z; acc.w += v.w;
    }
    float sc = 1.f / fmaxf((float)(end - beg), 1.f);
    acc.x *= sc; acc.y *= sc; acc.z *= sc; acc.w *= sc;
    *(float4*)(g_msum + (size_t)node * D + lane * 4) = acc;
}

// ---------------------------------------------------------------------------
// SAGE layer via tensor cores (3xTF32): out = relu(msum@Wl + bl + h@Wr)
// Block = 8 warps x 16 nodes = 128 nodes; each warp computes its 16x128 tile.
// Weight slabs (precomputed hi/lo tf32 planes) are flat-copied to SMEM in
// four K=64 stages. LAYER selects the slab set.
// ---------------------------------------------------------------------------
template <int LAYER, int SRC, int OUT>
__global__ void __launch_bounds__(256, 2) sage_mma(
    const float* __restrict__ x, const float* __restrict__ bl, int n) {
    extern __shared__ uint32_t sw[];
    uint32_t* sWhi = sw;
    uint32_t* sWlo = sw + SM_K * SM_PITCH;

    const int tid = threadIdx.x;
    const int wid = tid >> 5;
    const int lane = tid & 31;
    const int g = lane >> 2;     // group id: row within tile
    const int tig = lane & 3;    // thread in group: k / col selector

    const float* h = (SRC == 0) ? x : g_h1;
    float* out = (OUT == 1) ? g_h1 : g_h2;

    const int wbase = blockIdx.x * 128 + wid * 16;
    const int r0 = min(wbase + g, n - 1);
    const int r1 = min(wbase + g + 8, n - 1);

    // C fragments: 16 n-tiles x 4 regs, initialized with bias
    float c[16][4];
#pragma unroll
    for (int nt = 0; nt < 16; ++nt) {
        int col0 = nt * 8 + tig * 2;
        float b0 = bl[col0], b1 = bl[col0 + 1];
        c[nt][0] = b0; c[nt][1] = b1;
        c[nt][2] = b0; c[nt][3] = b1;
    }

#pragma unroll 1
    for (int pass = 0; pass < 4; ++pass) {
        // slab: mat = LAYER*2 + (0 for Wl, 1 for Wr); khalf = pass&1
        const int mat = LAYER * 2 + ((pass < 2) ? 0 : 1);
        const uint32_t* slab = g_planes + (mat * 2 + (pass & 1)) * SLAB_WORDS;
        const float* A = (pass < 2) ? g_msum : h;
        const int k0 = (pass & 1) * SM_K;

        __syncthreads();
        // flat copy of precomputed hi+lo planes (17408 words = 4352 float4)
        {
            const float4* src4 = (const float4*)slab;
            float4* dst4 = (float4*)sw;
            for (int idx = tid; idx < SLAB_WORDS / 4; idx += 256)
                dst4[idx] = src4[idx];
        }
        __syncthreads();

        const float* a0p = A + (size_t)r0 * D + k0;
        const float* a1p = A + (size_t)r1 * D + k0;

#pragma unroll
        for (int ks = 0; ks < 8; ++ks) {
            const int kc = ks * 8 + tig;
            float f0 = a0p[kc], f1 = a1p[kc];
            float f2v = a0p[kc + 4], f3 = a1p[kc + 4];
            uint32_t ah0 = f2tf32(f0), ah1 = f2tf32(f1);
            uint32_t ah2 = f2tf32(f2v), ah3 = f2tf32(f3);
            uint32_t al0 = f2tf32(f0 - __uint_as_float(ah0));
            uint32_t al1 = f2tf32(f1 - __uint_as_float(ah1));
            uint32_t al2 = f2tf32(f2v - __uint_as_float(ah2));
            uint32_t al3 = f2tf32(f3 - __uint_as_float(ah3));

            const int kb = (ks * 8 + tig) * SM_PITCH + g;
#pragma unroll
            for (int nt = 0; nt < 16; ++nt) {
                const int base = kb + nt * 8;
                uint32_t bh0 = sWhi[base];
                uint32_t bh1 = sWhi[base + 4 * SM_PITCH];
                uint32_t bl0 = sWlo[base];
                uint32_t bl1 = sWlo[base + 4 * SM_PITCH];
                mma_tf32(c[nt][0], c[nt][1], c[nt][2], c[nt][3],
                         ah0, ah1, ah2, ah3, bh0, bh1);
                mma_tf32(c[nt][0], c[nt][1], c[nt][2], c[nt][3],
                         ah0, ah1, ah2, ah3, bl0, bl1);
                mma_tf32(c[nt][0], c[nt][1], c[nt][2], c[nt][3],
                         al0, al1, al2, al3, bh0, bh1);
            }
        }
    }

    // epilogue: relu + store (rows g and g+8)
    const int row0 = wbase + g;
    const int row1 = wbase + g + 8;
    if (row0 < n) {
        float* o = out + (size_t)row0 * D + tig * 2;
#pragma unroll
        for (int nt = 0; nt < 16; ++nt)
            *(float2*)(o + nt * 8) =
                make_float2(fmaxf(c[nt][0], 0.f), fmaxf(c[nt][1], 0.f));
    }
    if (row1 < n) {
        float* o = out + (size_t)row1 * D + tig * 2;
#pragma unroll
        for (int nt = 0; nt < 16; ++nt)
            *(float2*)(o + nt * 8) =
                make_float2(fmaxf(c[nt][2], 0.f), fmaxf(c[nt][3], 0.f));
    }
}

// ---------------------------------------------------------------------------
// lin0: t = relu(g_h2 @ W0 + b0) -> g_msum[node*64 + col]  (SIMT FFMA2)
// ---------------------------------------------------------------------------
__global__ void __launch_bounds__(256) lin0_kernel(
    const float* __restrict__ W0, const float* __restrict__ b0, int n) {
    __shared__ float sW0[D * 32];
    __shared__ float sb[32];

    const int j0 = blockIdx.y * 32;
    for (int idx = threadIdx.x; idx < D * 32; idx += 256) {
        int k = idx >> 5, jj = idx & 31;
        sW0[idx] = W0[k * 64 + j0 + jj];
    }
    if (threadIdx.x < 32) sb[threadIdx.x] = b0[j0 + threadIdx.x];
    __syncthreads();

    int nd[4];
    const float4* hp[4];
#pragma unroll
    for (int i = 0; i < 4; i++) {
        nd[i] = blockIdx.x * 1024 + threadIdx.x + i * 256;
        int c = min(nd[i], n - 1);
        hp[i] = (const float4*)(g_h2 + (size_t)c * D);
    }

    unsigned long long acc[4][16];
#pragma unroll
    for (int p = 0; p < 16; p++) {
        unsigned long long b = pack2(sb[2 * p], sb[2 * p + 1]);
#pragma unroll
        for (int i = 0; i < 4; i++) acc[i][p] = b;
    }

    for (int k4 = 0; k4 < 32; ++k4) {
        float ar[4][4];
#pragma unroll
        for (int i = 0; i < 4; i++) {
            float4 q = hp[i][k4];
            ar[i][0] = q.x; ar[i][1] = q.y; ar[i][2] = q.z; ar[i][3] = q.w;
        }
#pragma unroll
        for (int kk = 0; kk < 4; ++kk) {
            const int kbase = (k4 * 4 + kk) * 32;
            ulonglong2 w0 = *(const ulonglong2*)&sW0[kbase + 0];
            ulonglong2 w1 = *(const ulonglong2*)&sW0[kbase + 4];
            ulonglong2 w2 = *(const ulonglong2*)&sW0[kbase + 8];
            ulonglong2 w3 = *(const ulonglong2*)&sW0[kbase + 12];
            ulonglong2 w4 = *(const ulonglong2*)&sW0[kbase + 16];
            ulonglong2 w5 = *(const ulonglong2*)&sW0[kbase + 20];
            ulonglong2 w6 = *(const ulonglong2*)&sW0[kbase + 24];
            ulonglong2 w7 = *(const ulonglong2*)&sW0[kbase + 28];
#pragma unroll
            for (int i = 0; i < 4; i++) {
                unsigned long long pr = pack2(ar[i][kk], ar[i][kk]);
                ffma2(acc[i][0],  pr, w0.x);
                ffma2(acc[i][1],  pr, w0.y);
                ffma2(acc[i][2],  pr, w1.x);
                ffma2(acc[i][3],  pr, w1.y);
                ffma2(acc[i][4],  pr, w2.x);
                ffma2(acc[i][5],  pr, w2.y);
                ffma2(acc[i][6],  pr, w3.x);
                ffma2(acc[i][7],  pr, w3.y);
                ffma2(acc[i][8],  pr, w4.x);
                ffma2(acc[i][9],  pr, w4.y);
                ffma2(acc[i][10], pr, w5.x);
                ffma2(acc[i][11], pr, w5.y);
                ffma2(acc[i][12], pr, w6.x);
                ffma2(acc[i][13], pr, w6.y);
                ffma2(acc[i][14], pr, w7.x);
                ffma2(acc[i][15], pr, w7.y);
            }
        }
    }

#pragma unroll
    for (int i = 0; i < 4; i++) {
        if (nd[i] < n) {
            float4* o = (float4*)(g_msum + (size_t)nd[i] * 64 + j0);
#pragma unroll
            for (int q = 0; q < 8; ++q) {
                float2 a = unpack2(acc[i][q * 2 + 0]);
                float2 b = unpack2(acc[i][q * 2 + 1]);
                o[q] = make_float4(fmaxf(a.x, 0.f), fmaxf(a.y, 0.f),
                                   fmaxf(b.x, 0.f), fmaxf(b.y, 0.f));
            }
        }
    }
}

// ---------------------------------------------------------------------------
// lin1: out = relu(t @ W1 + b1), t = g_msum[node*64 .. +64]
// ---------------------------------------------------------------------------
__global__ void __launch_bounds__(256) lin1_kernel(
    const float* __restrict__ W1, const float* __restrict__ b1,
    float* __restrict__ out, int n) {
    __shared__ float sW1[64 * 8];
    __shared__ float sb1[8];
    for (int idx = threadIdx.x; idx < 64 * 8; idx += 256) sW1[idx] = W1[idx];
    if (threadIdx.x < 8) sb1[threadIdx.x] = b1[threadIdx.x];
    __syncthreads();

    const int n0 = blockIdx.x * 256 + threadIdx.x;
    const int c0 = min(n0, n - 1);
    const float4* tp = (const float4*)(g_msum + (size_t)c0 * 64);

    unsigned long long o2[4];
#pragma unroll
    for (int p = 0; p < 4; p++) o2[p] = pack2(sb1[2 * p], sb1[2 * p + 1]);

#pragma unroll
    for (int k4 = 0; k4 < 16; ++k4) {
        float4 tv = tp[k4];
        float r[4] = {tv.x, tv.y, tv.z, tv.w};
#pragma unroll
        for (int kk = 0; kk < 4; ++kk) {
            const int kbase = (k4 * 4 + kk) * 8;
            ulonglong2 wA = *(const ulonglong2*)&sW1[kbase + 0];
            ulonglong2 wB = *(const ulonglong2*)&sW1[kbase + 4];
            unsigned long long pr = pack2(r[kk], r[kk]);
            ffma2(o2[0], pr, wA.x);
            ffma2(o2[1], pr, wA.y);
            ffma2(o2[2], pr, wB.x);
            ffma2(o2[3], pr, wB.y);
        }
    }

    if (n0 < n) {
        float4* op = (float4*)(out + (size_t)n0 * 8);
        float2 a = unpack2(o2[0]), b = unpack2(o2[1]);
        float2 c = unpack2(o2[2]), dd = unpack2(o2[3]);
        op[0] = make_float4(fmaxf(a.x, 0.f), fmaxf(a.y, 0.f),
                            fmaxf(b.x, 0.f), fmaxf(b.y, 0.f));
        op[1] = make_float4(fmaxf(c.x, 0.f), fmaxf(c.y, 0.f),
                            fmaxf(dd.x, 0.f), fmaxf(dd.y, 0.f));
    }
}

// ---------------------------------------------------------------------------
// Launcher (no allocation, graph-capturable)
// ---------------------------------------------------------------------------
extern "C" void kernel_launch(void* const* d_in, const int* in_sizes, int n_in,
                              void* d_out, int out_size) {
    const float* x    = (const float*)d_in[0];
    const void*  ei   = d_in[1];
    const float* s0Wl = (const float*)d_in[2];
    const float* s0bl = (const float*)d_in[3];
    const float* s0Wr = (const float*)d_in[4];
    const float* s1Wl = (const float*)d_in[5];
    const float* s1bl = (const float*)d_in[6];
    const float* s1Wr = (const float*)d_in[7];
    const float* l0W  = (const float*)d_in[8];
    const float* l0b  = (const float*)d_in[9];
    const float* l1W  = (const float*)d_in[10];
    const float* l1b  = (const float*)d_in[11];
    float* out = (float*)d_out;

    const int N = in_sizes[0] / D;
    const int E = in_sizes[1] / 2;
    const int NB = (N + SCAN_B - 1) / SCAN_B;

    cudaFuncSetAttribute(sage_mma<0, 0, 1>,
                         cudaFuncAttributeMaxDynamicSharedMemorySize, SM_BYTES);
    cudaFuncSetAttribute(sage_mma<1, 1, 2>,
                         cudaFuncAttributeMaxDynamicSharedMemorySize, SM_BYTES);

    // init (zero + dtype sniff) and weight-plane precompute
    init_kernel<<<(N + 255) / 256, 256>>>((const unsigned int*)ei, 2048, N);
    prep_planes_kernel<<<(4 * D * D + 255) / 256, 256>>>(s0Wl, s0Wr, s1Wl,
                                                         s1Wr);

    // CSR build (once per launch; shared by both layers)
    hist_kernel<<<(E + 255) / 256, 256>>>(ei, E, N);
    scan1_kernel<<<NB, SCAN_B>>>(N);
    scan2_kernel<<<1, 32>>>(NB, N, E);
    scan3_kernel<<<NB, SCAN_B>>>(N);
    fill_kernel<<<(E + 255) / 256, 256>>>(ei, E, N);

    const int agg_blocks = (int)(((long long)N * 32 + 255) / 256);
    const int mma_blocks = (N + 127) / 128;
    dim3 lgrid((N + 1023) / 1024, 2);

    // layer 0
    agg_kernel<0><<<agg_blocks, 256>>>(x, N);
    sage_mma<0, 0, 1><<<mma_blocks, 256, SM_BYTES>>>(x, s0bl, N);

    // layer 1
    agg_kernel<1><<<agg_blocks, 256>>>(x, N);
    sage_mma<1, 1, 2><<<mma_blocks, 256, SM_BYTES>>>(x, s1bl, N);

    // MLP head
    lin0_kernel<<<lgrid, 256>>>(l0W, l0b, N);
    lin1_kernel<<<(N + 255) / 256, 256>>>(l1W, l1b, out, N);
}

// round 14
// speedup vs baseline: 1.4606x; 1.3295x over previous
#include <cuda_runtime.h>
#include <cuda_bf16.h>
#include <stdint.h>

#define NN 100000
#define NE 600000
#define D 128
#define SCAN_B 1024

#define SM_PITCH 136
#define KPAIRS 64                              // K=128 -> 64 bf16x2 k-pairs
#define SLAB_WORDS (2 * KPAIRS * SM_PITCH)     // hi + lo planes, 17408 words
#define SM_BYTES (SLAB_WORDS * 4)              // 69632 B

// Scratch (device globals -- no runtime allocation allowed)
__device__ __align__(16) float g_msum[(size_t)NN * D];
__device__ __align__(16) float g_h1[(size_t)NN * D];
__device__ __align__(16) float g_h2[(size_t)NN * D];
__device__ __align__(16) uint32_t g_planes[4 * SLAB_WORDS];  // 4 matrices
__device__ int g_cnt[NN];
__device__ int g_fill[NN];
__device__ int g_rowptr[NN + 1];
__device__ int g_col[NE];
__device__ int g_is64;

// ---------------------------------------------------------------------------
// Packed f32x2 helpers (for the SIMT lin kernels)
// ---------------------------------------------------------------------------
__device__ __forceinline__ void ffma2(unsigned long long& acc,
                                      unsigned long long a,
                                      unsigned long long b) {
    asm("fma.rn.f32x2 %0, %1, %2, %0;" : "+l"(acc) : "l"(a), "l"(b));
}
__device__ __forceinline__ unsigned long long pack2(float lo, float hi) {
    unsigned long long r;
    asm("mov.b64 %0, {%1, %2};" : "=l"(r) : "f"(lo), "f"(hi));
    return r;
}
__device__ __forceinline__ float2 unpack2(unsigned long long v) {
    float lo, hi;
    asm("mov.b64 {%0, %1}, %2;" : "=f"(lo), "=f"(hi) : "l"(v));
    return make_float2(lo, hi);
}

// ---------------------------------------------------------------------------
// bf16 helpers: split f32x2 into bf16x2 hi word + bf16x2 residual word
// ---------------------------------------------------------------------------
__device__ __forceinline__ void split_bf2(float fx, float fy, uint32_t& hi,
                                          uint32_t& lo) {
    __nv_bfloat162 h = __floats2bfloat162_rn(fx, fy);   // .x = fx (low half)
    hi = *(uint32_t*)&h;
    float rx = fx - __bfloat162float(h.x);
    float ry = fy - __bfloat162float(h.y);
    __nv_bfloat162 l = __floats2bfloat162_rn(rx, ry);
    lo = *(uint32_t*)&l;
}

__device__ __forceinline__ void mma_bf16(float& c0, float& c1, float& c2,
                                         float& c3, uint32_t a0, uint32_t a1,
                                         uint32_t a2, uint32_t a3, uint32_t b0,
                                         uint32_t b1) {
    asm("mma.sync.aligned.m16n8k16.row.col.f32.bf16.bf16.f32 "
        "{%0,%1,%2,%3},{%4,%5,%6,%7},{%8,%9},{%0,%1,%2,%3};"
        : "+f"(c0), "+f"(c1), "+f"(c2), "+f"(c3)
        : "r"(a0), "r"(a1), "r"(a2), "r"(a3), "r"(b0), "r"(b1));
}

__device__ __forceinline__ int edge_at(const void* __restrict__ ei, int i) {
    if (g_is64) return (int)((const long long*)ei)[i];
    return ((const int*)ei)[i];
}

// ---------------------------------------------------------------------------
// init: zero cnt/fill arrays; block 0 also sniffs edge-index dtype
// ---------------------------------------------------------------------------
__global__ void init_kernel(const unsigned int* __restrict__ ei32, int npairs,
                            int n) {
    int i = blockIdx.x * blockDim.x + threadIdx.x;
    if (i < n) { g_cnt[i] = 0; g_fill[i] = 0; }
    if (blockIdx.x == 0) {
        __shared__ int any;
        if (threadIdx.x == 0) any = 0;
        __syncthreads();
        int found = 0;
        for (int j = threadIdx.x; j < npairs; j += blockDim.x)
            if (ei32[2 * j + 1] != 0u) found = 1;
        if (found) any = 1;   // benign race
        __syncthreads();
        if (threadIdx.x == 0) g_is64 = (any == 0);
    }
}

// ---------------------------------------------------------------------------
// Precompute bf16 hi/lo weight planes, SMEM-slab layout.
// Slab per matrix (mat: 0=s0Wl, 1=s0Wr, 2=s1Wl, 3=s1Wr), K=128 as 64 k-pairs:
//   hi plane [kp*PITCH + n] then lo plane at +KPAIRS*PITCH.
// Word (kp, n) packs (W[2kp][n], W[2kp+1][n]) as bf16x2.
// ---------------------------------------------------------------------------
__global__ void prep_planes_kernel(const float* __restrict__ Wl0,
                                   const float* __restrict__ Wr0,
                                   const float* __restrict__ Wl1,
                                   const float* __restrict__ Wr1) {
    int idx = blockIdx.x * blockDim.x + threadIdx.x;
    if (idx >= 4 * KPAIRS * D) return;
    int mat = idx >> 13;            // KPAIRS*D = 8192
    int e = idx & 8191;
    int kp = e >> 7, nn = e & 127;
    const float* W = (mat == 0) ? Wl0 : (mat == 1) ? Wr0 : (mat == 2) ? Wl1 : Wr1;
    float f0 = W[(2 * kp) * D + nn];
    float f1 = W[(2 * kp + 1) * D + nn];
    uint32_t hi, lo;
    split_bf2(f0, f1, hi, lo);
    uint32_t* slab = g_planes + mat * SLAB_WORDS;
    slab[kp * SM_PITCH + nn] = hi;
    slab[KPAIRS * SM_PITCH + kp * SM_PITCH + nn] = lo;
}

// ---------------------------------------------------------------------------
// CSR build: histogram -> block scan -> fill
// ---------------------------------------------------------------------------
__device__ int g_blocksum[128];
__device__ int g_blockoff[128];

__global__ void hist_kernel(const void* __restrict__ ei, int E, int n) {
    int e = blockIdx.x * blockDim.x + threadIdx.x;
    if (e >= E) return;
    unsigned d = min((unsigned)edge_at(ei, E + e), (unsigned)(n - 1));
    atomicAdd(&g_cnt[d], 1);
}

__global__ void __launch_bounds__(SCAN_B) scan1_kernel(int n) {
    __shared__ int sm[SCAN_B];
    int i = blockIdx.x * SCAN_B + threadIdx.x;
    sm[threadIdx.x] = (i < n) ? g_cnt[i] : 0;
    __syncthreads();
    for (int off = SCAN_B / 2; off > 0; off >>= 1) {
        if (threadIdx.x < off) sm[threadIdx.x] += sm[threadIdx.x + off];
        __syncthreads();
    }
    if (threadIdx.x == 0) g_blocksum[blockIdx.x] = sm[0];
}

__global__ void scan2_kernel(int nb, int n, int E) {
    if (threadIdx.x == 0) {
        int run = 0;
        for (int b = 0; b < nb; b++) { g_blockoff[b] = run; run += g_blocksum[b]; }
        g_rowptr[n] = E;
    }
}

__global__ void __launch_bounds__(SCAN_B) scan3_kernel(int n) {
    __shared__ int sm[SCAN_B];
    int i = blockIdx.x * SCAN_B + threadIdx.x;
    int v = (i < n) ? g_cnt[i] : 0;
    sm[threadIdx.x] = v;
    __syncthreads();
    for (int off = 1; off < SCAN_B; off <<= 1) {
        int t = 0;
        if ((int)threadIdx.x >= off) t = sm[threadIdx.x - off];
        __syncthreads();
        if ((int)threadIdx.x >= off) sm[threadIdx.x] += t;
        __syncthreads();
    }
    if (i < n) g_rowptr[i] = g_blockoff[blockIdx.x] + sm[threadIdx.x] - v;
}

__global__ void fill_kernel(const void* __restrict__ ei, int E, int n) {
    int e = blockIdx.x * blockDim.x + threadIdx.x;
    if (e >= E) return;
    unsigned s = min((unsigned)edge_at(ei, e), (unsigned)(n - 1));
    unsigned d = min((unsigned)edge_at(ei, E + e), (unsigned)(n - 1));
    int pos = g_rowptr[d] + atomicAdd(&g_fill[d], 1);
    g_col[pos] = (int)s;
}

// ---------------------------------------------------------------------------
// Gather aggregation: msum[i] = mean over in-neighbors of h[col].
// One warp per node; lane owns 16B. 4-deep unroll for MLP.
// ---------------------------------------------------------------------------
template <int SRC>
__global__ void __launch_bounds__(256) agg_kernel(const float* __restrict__ x,
                                                  int n) {
    int tid = blockIdx.x * blockDim.x + threadIdx.x;
    int node = tid >> 5;
    if (node >= n) return;
    int lane = tid & 31;
    const float* h = (SRC == 0) ? x : g_h1;
    int beg = g_rowptr[node], end = g_rowptr[node + 1];
    float4 acc = make_float4(0.f, 0.f, 0.f, 0.f);
    int k = beg;
    for (; k + 4 <= end; k += 4) {
        int c0 = g_col[k + 0], c1 = g_col[k + 1];
        int c2 = g_col[k + 2], c3 = g_col[k + 3];
        float4 v0 = *(const float4*)(h + (size_t)c0 * D + lane * 4);
        float4 v1 = *(const float4*)(h + (size_t)c1 * D + lane * 4);
        float4 v2 = *(const float4*)(h + (size_t)c2 * D + lane * 4);
        float4 v3 = *(const float4*)(h + (size_t)c3 * D + lane * 4);
        acc.x += v0.x + v1.x + v2.x + v3.x;
        acc.y += v0.y + v1.y + v2.y + v3.y;
        acc.z += v0.z + v1.z + v2.z + v3.z;
        acc.w += v0.w + v1.w + v2.w + v3.w;
    }
    for (; k < end; ++k) {
        int c = g_col[k];
        float4 v = *(const float4*)(h + (size_t)c * D + lane * 4);
        acc.x += v.x; acc.y += v.y; acc.z += v.z; acc.w += v.w;
    }
    float sc = 1.f / fmaxf((float)(end - beg), 1.f);
    acc.x *= sc; acc.y *= sc; acc.z *= sc; acc.w *= sc;
    *(float4*)(g_msum + (size_t)node * D + lane * 4) = acc;
}

// ---------------------------------------------------------------------------
// SAGE layer via tensor cores (3x-split BF16, m16n8k16):
//   out = relu(msum@Wl + bl + h@Wr)
// Block = 8 warps x 16 nodes = 128 nodes; warp computes its 16x128 tile.
// TWO passes (one per matrix): full K=128 bf16 hi/lo slab flat-copied to SMEM.
// D += Ahi*Bhi + Ahi*Blo + Alo*Bhi (lo*lo term ~2^-16, dropped).
// ---------------------------------------------------------------------------
template <int LAYER, int SRC, int OUT>
__global__ void __launch_bounds__(256, 2) sage_mma(
    const float* __restrict__ x, const float* __restrict__ bl, int n) {
    extern __shared__ uint32_t sw[];
    uint32_t* sWhi = sw;
    uint32_t* sWlo = sw + KPAIRS * SM_PITCH;

    const int tid = threadIdx.x;
    const int wid = tid >> 5;
    const int lane = tid & 31;
    const int g = lane >> 2;     // group id: row within tile
    const int tig = lane & 3;    // thread in group

    const float* h = (SRC == 0) ? x : g_h1;
    float* out = (OUT == 1) ? g_h1 : g_h2;

    const int wbase = blockIdx.x * 128 + wid * 16;
    const int r0 = min(wbase + g, n - 1);
    const int r1 = min(wbase + g + 8, n - 1);

    // C fragments: 16 n-tiles x 4 regs, initialized with bias
    float c[16][4];
#pragma unroll
    for (int nt = 0; nt < 16; ++nt) {
        int col0 = nt * 8 + tig * 2;
        float b0 = bl[col0], b1 = bl[col0 + 1];
        c[nt][0] = b0; c[nt][1] = b1;
        c[nt][2] = b0; c[nt][3] = b1;
    }

#pragma unroll 1
    for (int pass = 0; pass < 2; ++pass) {
        const uint32_t* slab = g_planes + (LAYER * 2 + pass) * SLAB_WORDS;
        const float* A = (pass == 0) ? g_msum : h;

        __syncthreads();
        // flat copy of precomputed hi+lo planes (17408 words = 4352 float4)
        {
            const float4* src4 = (const float4*)slab;
            float4* dst4 = (float4*)sw;
            for (int idx = tid; idx < SLAB_WORDS / 4; idx += 256)
                dst4[idx] = src4[idx];
        }
        __syncthreads();

        const float* a0p = A + (size_t)r0 * D;
        const float* a1p = A + (size_t)r1 * D;

#pragma unroll
        for (int ks = 0; ks < 8; ++ks) {
            const int kc = ks * 16 + tig * 2;
            // A fragments: rows r0/r1, cols kc..kc+1 and kc+8..kc+9
            float2 f0 = *(const float2*)(a0p + kc);
            float2 f1 = *(const float2*)(a1p + kc);
            float2 f2v = *(const float2*)(a0p + kc + 8);
            float2 f3 = *(const float2*)(a1p + kc + 8);
            uint32_t ah0, al0, ah1, al1, ah2, al2, ah3, al3;
            split_bf2(f0.x, f0.y, ah0, al0);
            split_bf2(f1.x, f1.y, ah1, al1);
            split_bf2(f2v.x, f2v.y, ah2, al2);
            split_bf2(f3.x, f3.y, ah3, al3);

            const int kb = (ks * 8 + tig) * SM_PITCH + g;
#pragma unroll
            for (int nt = 0; nt < 16; ++nt) {
                const int base = kb + nt * 8;
                uint32_t bh0 = sWhi[base];
                uint32_t bh1 = sWhi[base + 4 * SM_PITCH];
                uint32_t bl0 = sWlo[base];
                uint32_t bl1 = sWlo[base + 4 * SM_PITCH];
                mma_bf16(c[nt][0], c[nt][1], c[nt][2], c[nt][3],
                         ah0, ah1, ah2, ah3, bh0, bh1);
                mma_bf16(c[nt][0], c[nt][1], c[nt][2], c[nt][3],
                         ah0, ah1, ah2, ah3, bl0, bl1);
                mma_bf16(c[nt][0], c[nt][1], c[nt][2], c[nt][3],
                         al0, al1, al2, al3, bh0, bh1);
            }
        }
    }

    // epilogue: relu + store (rows g and g+8)
    const int row0 = wbase + g;
    const int row1 = wbase + g + 8;
    if (row0 < n) {
        float* o = out + (size_t)row0 * D + tig * 2;
#pragma unroll
        for (int nt = 0; nt < 16; ++nt)
            *(float2*)(o + nt * 8) =
                make_float2(fmaxf(c[nt][0], 0.f), fmaxf(c[nt][1], 0.f));
    }
    if (row1 < n) {
        float* o = out + (size_t)row1 * D + tig * 2;
#pragma unroll
        for (int nt = 0; nt < 16; ++nt)
            *(float2*)(o + nt * 8) =
                make_float2(fmaxf(c[nt][2], 0.f), fmaxf(c[nt][3], 0.f));
    }
}

// ---------------------------------------------------------------------------
// lin0: t = relu(g_h2 @ W0 + b0) -> g_msum[node*64 + col]  (SIMT FFMA2)
// ---------------------------------------------------------------------------
__global__ void __launch_bounds__(256) lin0_kernel(
    const float* __restrict__ W0, const float* __restrict__ b0, int n) {
    __shared__ float sW0[D * 32];
    __shared__ float sb[32];

    const int j0 = blockIdx.y * 32;
    for (int idx = threadIdx.x; idx < D * 32; idx += 256) {
        int k = idx >> 5, jj = idx & 31;
        sW0[idx] = W0[k * 64 + j0 + jj];
    }
    if (threadIdx.x < 32) sb[threadIdx.x] = b0[j0 + threadIdx.x];
    __syncthreads();

    int nd[4];
    const float4* hp[4];
#pragma unroll
    for (int i = 0; i < 4; i++) {
        nd[i] = blockIdx.x * 1024 + threadIdx.x + i * 256;
        int c = min(nd[i], n - 1);
        hp[i] = (const float4*)(g_h2 + (size_t)c * D);
    }

    unsigned long long acc[4][16];
#pragma unroll
    for (int p = 0; p < 16; p++) {
        unsigned long long b = pack2(sb[2 * p], sb[2 * p + 1]);
#pragma unroll
        for (int i = 0; i < 4; i++) acc[i][p] = b;
    }

    for (int k4 = 0; k4 < 32; ++k4) {
        float ar[4][4];
#pragma unroll
        for (int i = 0; i < 4; i++) {
            float4 q = hp[i][k4];
            ar[i][0] = q.x; ar[i][1] = q.y; ar[i][2] = q.z; ar[i][3] = q.w;
        }
#pragma unroll
        for (int kk = 0; kk < 4; ++kk) {
            const int kbase = (k4 * 4 + kk) * 32;
            ulonglong2 w0 = *(const ulonglong2*)&sW0[kbase + 0];
            ulonglong2 w1 = *(const ulonglong2*)&sW0[kbase + 4];
            ulonglong2 w2 = *(const ulonglong2*)&sW0[kbase + 8];
            ulonglong2 w3 = *(const ulonglong2*)&sW0[kbase + 12];
            ulonglong2 w4 = *(const ulonglong2*)&sW0[kbase + 16];
            ulonglong2 w5 = *(const ulonglong2*)&sW0[kbase + 20];
            ulonglong2 w6 = *(const ulonglong2*)&sW0[kbase + 24];
            ulonglong2 w7 = *(const ulonglong2*)&sW0[kbase + 28];
#pragma unroll
            for (int i = 0; i < 4; i++) {
                unsigned long long pr = pack2(ar[i][kk], ar[i][kk]);
                ffma2(acc[i][0],  pr, w0.x);
                ffma2(acc[i][1],  pr, w0.y);
                ffma2(acc[i][2],  pr, w1.x);
                ffma2(acc[i][3],  pr, w1.y);
                ffma2(acc[i][4],  pr, w2.x);
                ffma2(acc[i][5],  pr, w2.y);
                ffma2(acc[i][6],  pr, w3.x);
                ffma2(acc[i][7],  pr, w3.y);
                ffma2(acc[i][8],  pr, w4.x);
                ffma2(acc[i][9],  pr, w4.y);
                ffma2(acc[i][10], pr, w5.x);
                ffma2(acc[i][11], pr, w5.y);
                ffma2(acc[i][12], pr, w6.x);
                ffma2(acc[i][13], pr, w6.y);
                ffma2(acc[i][14], pr, w7.x);
                ffma2(acc[i][15], pr, w7.y);
            }
        }
    }

#pragma unroll
    for (int i = 0; i < 4; i++) {
        if (nd[i] < n) {
            float4* o = (float4*)(g_msum + (size_t)nd[i] * 64 + j0);
#pragma unroll
            for (int q = 0; q < 8; ++q) {
                float2 a = unpack2(acc[i][q * 2 + 0]);
                float2 b = unpack2(acc[i][q * 2 + 1]);
                o[q] = make_float4(fmaxf(a.x, 0.f), fmaxf(a.y, 0.f),
                                   fmaxf(b.x, 0.f), fmaxf(b.y, 0.f));
            }
        }
    }
}

// ---------------------------------------------------------------------------
// lin1: out = relu(t @ W1 + b1), t = g_msum[node*64 .. +64]
// ---------------------------------------------------------------------------
__global__ void __launch_bounds__(256) lin1_kernel(
    const float* __restrict__ W1, const float* __restrict__ b1,
    float* __restrict__ out, int n) {
    __shared__ float sW1[64 * 8];
    __shared__ float sb1[8];
    for (int idx = threadIdx.x; idx < 64 * 8; idx += 256) sW1[idx] = W1[idx];
    if (threadIdx.x < 8) sb1[threadIdx.x] = b1[threadIdx.x];
    __syncthreads();

    const int n0 = blockIdx.x * 256 + threadIdx.x;
    const int c0 = min(n0, n - 1);
    const float4* tp = (const float4*)(g_msum + (size_t)c0 * 64);

    unsigned long long o2[4];
#pragma unroll
    for (int p = 0; p < 4; p++) o2[p] = pack2(sb1[2 * p], sb1[2 * p + 1]);

#pragma unroll
    for (int k4 = 0; k4 < 16; ++k4) {
        float4 tv = tp[k4];
        float r[4] = {tv.x, tv.y, tv.z, tv.w};
#pragma unroll
        for (int kk = 0; kk < 4; ++kk) {
            const int kbase = (k4 * 4 + kk) * 8;
            ulonglong2 wA = *(const ulonglong2*)&sW1[kbase + 0];
            ulonglong2 wB = *(const ulonglong2*)&sW1[kbase + 4];
            unsigned long long pr = pack2(r[kk], r[kk]);
            ffma2(o2[0], pr, wA.x);
            ffma2(o2[1], pr, wA.y);
            ffma2(o2[2], pr, wB.x);
            ffma2(o2[3], pr, wB.y);
        }
    }

    if (n0 < n) {
        float4* op = (float4*)(out + (size_t)n0 * 8);
        float2 a = unpack2(o2[0]), b = unpack2(o2[1]);
        float2 c = unpack2(o2[2]), dd = unpack2(o2[3]);
        op[0] = make_float4(fmaxf(a.x, 0.f), fmaxf(a.y, 0.f),
                            fmaxf(b.x, 0.f), fmaxf(b.y, 0.f));
        op[1] = make_float4(fmaxf(c.x, 0.f), fmaxf(c.y, 0.f),
                            fmaxf(dd.x, 0.f), fmaxf(dd.y, 0.f));
    }
}

// ---------------------------------------------------------------------------
// Launcher (no allocation, graph-capturable)
// ---------------------------------------------------------------------------
extern "C" void kernel_launch(void* const* d_in, const int* in_sizes, int n_in,
                              void* d_out, int out_size) {
    const float* x    = (const float*)d_in[0];
    const void*  ei   = d_in[1];
    const float* s0Wl = (const float*)d_in[2];
    const float* s0bl = (const float*)d_in[3];
    const float* s0Wr = (const float*)d_in[4];
    const float* s1Wl = (const float*)d_in[5];
    const float* s1bl = (const float*)d_in[6];
    const float* s1Wr = (const float*)d_in[7];
    const float* l0W  = (const float*)d_in[8];
    const float* l0b  = (const float*)d_in[9];
    const float* l1W  = (const float*)d_in[10];
    const float* l1b  = (const float*)d_in[11];
    float* out = (float*)d_out;

    const int N = in_sizes[0] / D;
    const int E = in_sizes[1] / 2;
    const int NB = (N + SCAN_B - 1) / SCAN_B;

    cudaFuncSetAttribute(sage_mma<0, 0, 1>,
                         cudaFuncAttributeMaxDynamicSharedMemorySize, SM_BYTES);
    cudaFuncSetAttribute(sage_mma<1, 1, 2>,
                         cudaFuncAttributeMaxDynamicSharedMemorySize, SM_BYTES);

    // init (zero + dtype sniff) and weight-plane precompute
    init_kernel<<<(N + 255) / 256, 256>>>((const unsigned int*)ei, 2048, N);
    prep_planes_kernel<<<(4 * KPAIRS * D + 255) / 256, 256>>>(s0Wl, s0Wr,
                                                              s1Wl, s1Wr);

    // CSR build (once per launch; shared by both layers)
    hist_kernel<<<(E + 255) / 256, 256>>>(ei, E, N);
    scan1_kernel<<<NB, SCAN_B>>>(N);
    scan2_kernel<<<1, 32>>>(NB, N, E);
    scan3_kernel<<<NB, SCAN_B>>>(N);
    fill_kernel<<<(E + 255) / 256, 256>>>(ei, E, N);

    const int agg_blocks = (int)(((long long)N * 32 + 255) / 256);
    const int mma_blocks = (N + 127) / 128;
    dim3 lgrid((N + 1023) / 1024, 2);

    // layer 0
    agg_kernel<0><<<agg_blocks, 256>>>(x, N);
    sage_mma<0, 0, 1><<<mma_blocks, 256, SM_BYTES>>>(x, s0bl, N);

    // layer 1
    agg_kernel<1><<<agg_blocks, 256>>>(x, N);
    sage_mma<1, 1, 2><<<mma_blocks, 256, SM_BYTES>>>(x, s1bl, N);

    // MLP head
    lin0_kernel<<<lgrid, 256>>>(l0W, l0b, N);
    lin1_kernel<<<(N + 255) / 256, 256>>>(l1W, l1b, out, N);
}

// round 15
// speedup vs baseline: 1.8324x; 1.2545x over previous
#include <cuda_runtime.h>
#include <cuda_bf16.h>
#include <stdint.h>

#define NN 100000
#define NE 600000
#define D 128
#define SCAN_B 1024

#define SM_PITCH 136
#define KPAIRS 64                              // K=128 -> 64 bf16x2 k-pairs
#define SLAB_WORDS (2 * KPAIRS * SM_PITCH)     // hi + lo planes, 17408 words
#define SM_BYTES (SLAB_WORDS * 4)              // 69632 B

// MLP-head slabs
#define L0_PITCH 72
#define L0_WORDS (2 * 64 * L0_PITCH)           // 9216 words (hi+lo)
#define L1_PITCH 8
#define L1_WORDS (2 * 32 * L1_PITCH)           // 512 words

// Scratch (device globals -- no runtime allocation allowed)
__device__ __align__(16) float g_msum[(size_t)NN * D];
__device__ __align__(16) float g_h1[(size_t)NN * D];
__device__ __align__(16) float g_h2[(size_t)NN * D];
__device__ __align__(16) uint32_t g_planes[4 * SLAB_WORDS];  // 4 sage matrices
__device__ __align__(16) uint32_t g_l0planes[L0_WORDS];
__device__ __align__(16) uint32_t g_l1planes[L1_WORDS];
__device__ int g_cnt[NN];
__device__ int g_fill[NN];
__device__ int g_rowptr[NN + 1];
__device__ int g_col[NE];
__device__ int g_blocksum[128];
__device__ int g_blockoff[128];
__device__ int g_is64;

// ---------------------------------------------------------------------------
// bf16 helpers: split f32x2 into bf16x2 hi word + bf16x2 residual word
// ---------------------------------------------------------------------------
__device__ __forceinline__ void split_bf2(float fx, float fy, uint32_t& hi,
                                          uint32_t& lo) {
    __nv_bfloat162 h = __floats2bfloat162_rn(fx, fy);   // .x = fx (low half)
    hi = *(uint32_t*)&h;
    float rx = fx - __bfloat162float(h.x);
    float ry = fy - __bfloat162float(h.y);
    __nv_bfloat162 l = __floats2bfloat162_rn(rx, ry);
    lo = *(uint32_t*)&l;
}

__device__ __forceinline__ void mma_bf16(float& c0, float& c1, float& c2,
                                         float& c3, uint32_t a0, uint32_t a1,
                                         uint32_t a2, uint32_t a3, uint32_t b0,
                                         uint32_t b1) {
    asm("mma.sync.aligned.m16n8k16.row.col.f32.bf16.bf16.f32 "
        "{%0,%1,%2,%3},{%4,%5,%6,%7},{%8,%9},{%0,%1,%2,%3};"
        : "+f"(c0), "+f"(c1), "+f"(c2), "+f"(c3)
        : "r"(a0), "r"(a1), "r"(a2), "r"(a3), "r"(b0), "r"(b1));
}

__device__ __forceinline__ int edge_at(const void* __restrict__ ei, int i) {
    if (g_is64) return (int)((const long long*)ei)[i];
    return ((const int*)ei)[i];
}

// ---------------------------------------------------------------------------
// init: zero cnt/fill arrays; block 0 also sniffs edge-index dtype
// ---------------------------------------------------------------------------
__global__ void init_kernel(const unsigned int* __restrict__ ei32, int npairs,
                            int n) {
    int i = blockIdx.x * blockDim.x + threadIdx.x;
    if (i < n) { g_cnt[i] = 0; g_fill[i] = 0; }
    if (blockIdx.x == 0) {
        __shared__ int any;
        if (threadIdx.x == 0) any = 0;
        __syncthreads();
        int found = 0;
        for (int j = threadIdx.x; j < npairs; j += blockDim.x)
            if (ei32[2 * j + 1] != 0u) found = 1;
        if (found) any = 1;   // benign race
        __syncthreads();
        if (threadIdx.x == 0) g_is64 = (any == 0);
    }
}

// ---------------------------------------------------------------------------
// Precompute bf16 hi/lo weight planes for the sage matrices (SMEM-slab layout).
// Word (kp, n) packs (W[2kp][n], W[2kp+1][n]) as bf16x2.
// ---------------------------------------------------------------------------
__global__ void prep_planes_kernel(const float* __restrict__ Wl0,
                                   const float* __restrict__ Wr0,
                                   const float* __restrict__ Wl1,
                                   const float* __restrict__ Wr1) {
    int idx = blockIdx.x * blockDim.x + threadIdx.x;
    if (idx >= 4 * KPAIRS * D) return;
    int mat = idx >> 13;            // KPAIRS*D = 8192
    int e = idx & 8191;
    int kp = e >> 7, nn = e & 127;
    const float* W = (mat == 0) ? Wl0 : (mat == 1) ? Wr0 : (mat == 2) ? Wl1 : Wr1;
    float f0 = W[(2 * kp) * D + nn];
    float f1 = W[(2 * kp + 1) * D + nn];
    uint32_t hi, lo;
    split_bf2(f0, f1, hi, lo);
    uint32_t* slab = g_planes + mat * SLAB_WORDS;
    slab[kp * SM_PITCH + nn] = hi;
    slab[KPAIRS * SM_PITCH + kp * SM_PITCH + nn] = lo;
}

// ---------------------------------------------------------------------------
// Precompute hi/lo planes for the MLP head (W0 128x64 pitch 72, W1 64x8 pitch 8)
// ---------------------------------------------------------------------------
__global__ void prep_lin_kernel(const float* __restrict__ W0,
                                const float* __restrict__ W1) {
    int idx = blockIdx.x * blockDim.x + threadIdx.x;
    if (idx < 64 * 64) {          // W0: 64 kpairs x 64 cols
        int kp = idx >> 6, nn = idx & 63;
        float f0 = W0[(2 * kp) * 64 + nn];
        float f1 = W0[(2 * kp + 1) * 64 + nn];
        uint32_t hi, lo;
        split_bf2(f0, f1, hi, lo);
        g_l0planes[kp * L0_PITCH + nn] = hi;
        g_l0planes[64 * L0_PITCH + kp * L0_PITCH + nn] = lo;
    }
    int idx1 = idx - 64 * 64;
    if (idx1 >= 0 && idx1 < 32 * 8) {  // W1: 32 kpairs x 8 cols
        int kp = idx1 >> 3, nn = idx1 & 7;
        float f0 = W1[(2 * kp) * 8 + nn];
        float f1 = W1[(2 * kp + 1) * 8 + nn];
        uint32_t hi, lo;
        split_bf2(f0, f1, hi, lo);
        g_l1planes[kp * L1_PITCH + nn] = hi;
        g_l1planes[32 * L1_PITCH + kp * L1_PITCH + nn] = lo;
    }
}

// ---------------------------------------------------------------------------
// CSR build: histogram -> block scan -> fill
// ---------------------------------------------------------------------------
__global__ void hist_kernel(const void* __restrict__ ei, int E, int n) {
    int e = blockIdx.x * blockDim.x + threadIdx.x;
    if (e >= E) return;
    unsigned d = min((unsigned)edge_at(ei, E + e), (unsigned)(n - 1));
    atomicAdd(&g_cnt[d], 1);
}

__global__ void __launch_bounds__(SCAN_B) scan1_kernel(int n) {
    __shared__ int sm[SCAN_B];
    int i = blockIdx.x * SCAN_B + threadIdx.x;
    sm[threadIdx.x] = (i < n) ? g_cnt[i] : 0;
    __syncthreads();
    for (int off = SCAN_B / 2; off > 0; off >>= 1) {
        if (threadIdx.x < off) sm[threadIdx.x] += sm[threadIdx.x + off];
        __syncthreads();
    }
    if (threadIdx.x == 0) g_blocksum[blockIdx.x] = sm[0];
}

__global__ void scan2_kernel(int nb, int n, int E) {
    if (threadIdx.x == 0) {
        int run = 0;
        for (int b = 0; b < nb; b++) { g_blockoff[b] = run; run += g_blocksum[b]; }
        g_rowptr[n] = E;
    }
}

__global__ void __launch_bounds__(SCAN_B) scan3_kernel(int n) {
    __shared__ int sm[SCAN_B];
    int i = blockIdx.x * SCAN_B + threadIdx.x;
    int v = (i < n) ? g_cnt[i] : 0;
    sm[threadIdx.x] = v;
    __syncthreads();
    for (int off = 1; off < SCAN_B; off <<= 1) {
        int t = 0;
        if ((int)threadIdx.x >= off) t = sm[threadIdx.x - off];
        __syncthreads();
        if ((int)threadIdx.x >= off) sm[threadIdx.x] += t;
        __syncthreads();
    }
    if (i < n) g_rowptr[i] = g_blockoff[blockIdx.x] + sm[threadIdx.x] - v;
}

__global__ void fill_kernel(const void* __restrict__ ei, int E, int n) {
    int e = blockIdx.x * blockDim.x + threadIdx.x;
    if (e >= E) return;
    unsigned s = min((unsigned)edge_at(ei, e), (unsigned)(n - 1));
    unsigned d = min((unsigned)edge_at(ei, E + e), (unsigned)(n - 1));
    int pos = g_rowptr[d] + atomicAdd(&g_fill[d], 1);
    g_col[pos] = (int)s;
}

// ---------------------------------------------------------------------------
// Gather aggregation: msum[i] = mean over in-neighbors of h[col].
// ---------------------------------------------------------------------------
template <int SRC>
__global__ void __launch_bounds__(256) agg_kernel(const float* __restrict__ x,
                                                  int n) {
    int tid = blockIdx.x * blockDim.x + threadIdx.x;
    int node = tid >> 5;
    if (node >= n) return;
    int lane = tid & 31;
    const float* h = (SRC == 0) ? x : g_h1;
    int beg = g_rowptr[node], end = g_rowptr[node + 1];
    float4 acc = make_float4(0.f, 0.f, 0.f, 0.f);
    int k = beg;
    for (; k + 4 <= end; k += 4) {
        int c0 = g_col[k + 0], c1 = g_col[k + 1];
        int c2 = g_col[k + 2], c3 = g_col[k + 3];
        float4 v0 = *(const float4*)(h + (size_t)c0 * D + lane * 4);
        float4 v1 = *(const float4*)(h + (size_t)c1 * D + lane * 4);
        float4 v2 = *(const float4*)(h + (size_t)c2 * D + lane * 4);
        float4 v3 = *(const float4*)(h + (size_t)c3 * D + lane * 4);
        acc.x += v0.x + v1.x + v2.x + v3.x;
        acc.y += v0.y + v1.y + v2.y + v3.y;
        acc.z += v0.z + v1.z + v2.z + v3.z;
        acc.w += v0.w + v1.w + v2.w + v3.w;
    }
    for (; k < end; ++k) {
        int c = g_col[k];
        float4 v = *(const float4*)(h + (size_t)c * D + lane * 4);
        acc.x += v.x; acc.y += v.y; acc.z += v.z; acc.w += v.w;
    }
    float sc = 1.f / fmaxf((float)(end - beg), 1.f);
    acc.x *= sc; acc.y *= sc; acc.z *= sc; acc.w *= sc;
    *(float4*)(g_msum + (size_t)node * D + lane * 4) = acc;
}

// ---------------------------------------------------------------------------
// SAGE layer via tensor cores (3x-split BF16, m16n8k16):
//   out = relu(msum@Wl + bl + h@Wr)
// ---------------------------------------------------------------------------
template <int LAYER, int SRC, int OUT>
__global__ void __launch_bounds__(256, 2) sage_mma(
    const float* __restrict__ x, const float* __restrict__ bl, int n) {
    extern __shared__ uint32_t sw[];
    uint32_t* sWhi = sw;
    uint32_t* sWlo = sw + KPAIRS * SM_PITCH;

    const int tid = threadIdx.x;
    const int wid = tid >> 5;
    const int lane = tid & 31;
    const int g = lane >> 2;     // group id: row within tile
    const int tig = lane & 3;    // thread in group

    const float* h = (SRC == 0) ? x : g_h1;
    float* out = (OUT == 1) ? g_h1 : g_h2;

    const int wbase = blockIdx.x * 128 + wid * 16;
    const int r0 = min(wbase + g, n - 1);
    const int r1 = min(wbase + g + 8, n - 1);

    float c[16][4];
#pragma unroll
    for (int nt = 0; nt < 16; ++nt) {
        int col0 = nt * 8 + tig * 2;
        float b0 = bl[col0], b1 = bl[col0 + 1];
        c[nt][0] = b0; c[nt][1] = b1;
        c[nt][2] = b0; c[nt][3] = b1;
    }

#pragma unroll 1
    for (int pass = 0; pass < 2; ++pass) {
        const uint32_t* slab = g_planes + (LAYER * 2 + pass) * SLAB_WORDS;
        const float* A = (pass == 0) ? g_msum : h;

        __syncthreads();
        {
            const float4* src4 = (const float4*)slab;
            float4* dst4 = (float4*)sw;
            for (int idx = tid; idx < SLAB_WORDS / 4; idx += 256)
                dst4[idx] = src4[idx];
        }
        __syncthreads();

        const float* a0p = A + (size_t)r0 * D;
        const float* a1p = A + (size_t)r1 * D;

#pragma unroll
        for (int ks = 0; ks < 8; ++ks) {
            const int kc = ks * 16 + tig * 2;
            float2 f0 = *(const float2*)(a0p + kc);
            float2 f1 = *(const float2*)(a1p + kc);
            float2 f2v = *(const float2*)(a0p + kc + 8);
            float2 f3 = *(const float2*)(a1p + kc + 8);
            uint32_t ah0, al0, ah1, al1, ah2, al2, ah3, al3;
            split_bf2(f0.x, f0.y, ah0, al0);
            split_bf2(f1.x, f1.y, ah1, al1);
            split_bf2(f2v.x, f2v.y, ah2, al2);
            split_bf2(f3.x, f3.y, ah3, al3);

            const int kb = (ks * 8 + tig) * SM_PITCH + g;
#pragma unroll
            for (int nt = 0; nt < 16; ++nt) {
                const int base = kb + nt * 8;
                uint32_t bh0 = sWhi[base];
                uint32_t bh1 = sWhi[base + 4 * SM_PITCH];
                uint32_t bl0 = sWlo[base];
                uint32_t bl1 = sWlo[base + 4 * SM_PITCH];
                mma_bf16(c[nt][0], c[nt][1], c[nt][2], c[nt][3],
                         ah0, ah1, ah2, ah3, bh0, bh1);
                mma_bf16(c[nt][0], c[nt][1], c[nt][2], c[nt][3],
                         ah0, ah1, ah2, ah3, bl0, bl1);
                mma_bf16(c[nt][0], c[nt][1], c[nt][2], c[nt][3],
                         al0, al1, al2, al3, bh0, bh1);
            }
        }
    }

    const int row0 = wbase + g;
    const int row1 = wbase + g + 8;
    if (row0 < n) {
        float* o = out + (size_t)row0 * D + tig * 2;
#pragma unroll
        for (int nt = 0; nt < 16; ++nt)
            *(float2*)(o + nt * 8) =
                make_float2(fmaxf(c[nt][0], 0.f), fmaxf(c[nt][1], 0.f));
    }
    if (row1 < n) {
        float* o = out + (size_t)row1 * D + tig * 2;
#pragma unroll
        for (int nt = 0; nt < 16; ++nt)
            *(float2*)(o + nt * 8) =
                make_float2(fmaxf(c[nt][2], 0.f), fmaxf(c[nt][3], 0.f));
    }
}

// ---------------------------------------------------------------------------
// Fused MLP head via tensor cores (3x-split BF16):
//   out = relu( relu(h2@W0 + b0) @ W1 + b1 )
// Block = 8 warps x 16 rows = 128 nodes. The intermediate t lives entirely in
// C fragments: the m16n8 C layout equals the m16n8k16 A layout, so t feeds the
// second GEMM with only register relu + bf16-split (no SMEM/global roundtrip).
// ---------------------------------------------------------------------------
__global__ void __launch_bounds__(256, 2) lin_mma(
    const float* __restrict__ b0v, const float* __restrict__ b1v,
    float* __restrict__ out, int n) {
    __shared__ uint32_t s0[L0_WORDS];   // W0 hi plane then lo plane
    __shared__ uint32_t s1[L1_WORDS];   // W1 hi plane then lo plane

    const int tid = threadIdx.x;
    const int wid = tid >> 5;
    const int lane = tid & 31;
    const int g = lane >> 2;
    const int tig = lane & 3;

    // stage both weight slabs (flat copies)
    {
        const float4* src4 = (const float4*)g_l0planes;
        float4* dst4 = (float4*)s0;
        for (int idx = tid; idx < L0_WORDS / 4; idx += 256) dst4[idx] = src4[idx];
        const float4* src1 = (const float4*)g_l1planes;
        float4* dst1 = (float4*)s1;
        for (int idx = tid; idx < L1_WORDS / 4; idx += 256) dst1[idx] = src1[idx];
    }
    __syncthreads();

    const uint32_t* s0hi = s0;
    const uint32_t* s0lo = s0 + 64 * L0_PITCH;
    const uint32_t* s1hi = s1;
    const uint32_t* s1lo = s1 + 32 * L1_PITCH;

    const int wbase = blockIdx.x * 128 + wid * 16;
    const int r0 = min(wbase + g, n - 1);
    const int r1 = min(wbase + g + 8, n - 1);

    // ---- GEMM 1: t = h2 @ W0 + b0 (64 cols = 8 n-tiles) ----
    float t[8][4];
#pragma unroll
    for (int nt = 0; nt < 8; ++nt) {
        int col0 = nt * 8 + tig * 2;
        float b0 = b0v[col0], b1 = b0v[col0 + 1];
        t[nt][0] = b0; t[nt][1] = b1;
        t[nt][2] = b0; t[nt][3] = b1;
    }

    const float* a0p = g_h2 + (size_t)r0 * D;
    const float* a1p = g_h2 + (size_t)r1 * D;

#pragma unroll
    for (int ks = 0; ks < 8; ++ks) {
        const int kc = ks * 16 + tig * 2;
        float2 f0 = *(const float2*)(a0p + kc);
        float2 f1 = *(const float2*)(a1p + kc);
        float2 f2v = *(const float2*)(a0p + kc + 8);
        float2 f3 = *(const float2*)(a1p + kc + 8);
        uint32_t ah0, al0, ah1, al1, ah2, al2, ah3, al3;
        split_bf2(f0.x, f0.y, ah0, al0);
        split_bf2(f1.x, f1.y, ah1, al1);
        split_bf2(f2v.x, f2v.y, ah2, al2);
        split_bf2(f3.x, f3.y, ah3, al3);

        const int kb = (ks * 8 + tig) * L0_PITCH + g;
#pragma unroll
        for (int nt = 0; nt < 8; ++nt) {
            const int base = kb + nt * 8;
            uint32_t bh0 = s0hi[base];
            uint32_t bh1 = s0hi[base + 4 * L0_PITCH];
            uint32_t bl0 = s0lo[base];
            uint32_t bl1 = s0lo[base + 4 * L0_PITCH];
            mma_bf16(t[nt][0], t[nt][1], t[nt][2], t[nt][3],
                     ah0, ah1, ah2, ah3, bh0, bh1);
            mma_bf16(t[nt][0], t[nt][1], t[nt][2], t[nt][3],
                     ah0, ah1, ah2, ah3, bl0, bl1);
            mma_bf16(t[nt][0], t[nt][1], t[nt][2], t[nt][3],
                     al0, al1, al2, al3, bh0, bh1);
        }
    }

    // ---- GEMM 2: o = relu(t) @ W1 + b1 (8 cols = 1 n-tile, K=64) ----
    float o[4];
    {
        float b0 = b1v[tig * 2], b1 = b1v[tig * 2 + 1];
        o[0] = b0; o[1] = b1; o[2] = b0; o[3] = b1;
    }

#pragma unroll
    for (int j = 0; j < 4; ++j) {   // k-chunks of 16 over K=64
        // A fragments directly from C fragments (identical layouts):
        // a0 = (g, 16j+2tig..+1)   = relu(t[2j][0..1])
        // a1 = (g+8, same cols)    = relu(t[2j][2..3])
        // a2 = (g, 16j+8+2tig..+1) = relu(t[2j+1][0..1])
        // a3 = (g+8, same)         = relu(t[2j+1][2..3])
        uint32_t ah0, al0, ah1, al1, ah2, al2, ah3, al3;
        split_bf2(fmaxf(t[2 * j][0], 0.f), fmaxf(t[2 * j][1], 0.f), ah0, al0);
        split_bf2(fmaxf(t[2 * j][2], 0.f), fmaxf(t[2 * j][3], 0.f), ah1, al1);
        split_bf2(fmaxf(t[2 * j + 1][0], 0.f), fmaxf(t[2 * j + 1][1], 0.f),
                  ah2, al2);
        split_bf2(fmaxf(t[2 * j + 1][2], 0.f), fmaxf(t[2 * j + 1][3], 0.f),
                  ah3, al3);

        const int kb = (j * 8 + tig) * L1_PITCH + g;
        uint32_t bh0 = s1hi[kb];
        uint32_t bh1 = s1hi[kb + 4 * L1_PITCH];
        uint32_t bl0 = s1lo[kb];
        uint32_t bl1 = s1lo[kb + 4 * L1_PITCH];
        mma_bf16(o[0], o[1], o[2], o[3], ah0, ah1, ah2, ah3, bh0, bh1);
        mma_bf16(o[0], o[1], o[2], o[3], ah0, ah1, ah2, ah3, bl0, bl1);
        mma_bf16(o[0], o[1], o[2], o[3], al0, al1, al2, al3, bh0, bh1);
    }

    // store: row g -> o[0..1], row g+8 -> o[2..3], cols tig*2..+1
    const int row0 = wbase + g;
    const int row1 = wbase + g + 8;
    if (row0 < n)
        *(float2*)(out + (size_t)row0 * 8 + tig * 2) =
            make_float2(fmaxf(o[0], 0.f), fmaxf(o[1], 0.f));
    if (row1 < n)
        *(float2*)(out + (size_t)row1 * 8 + tig * 2) =
            make_float2(fmaxf(o[2], 0.f), fmaxf(o[3], 0.f));
}

// ---------------------------------------------------------------------------
// Launcher (no allocation, graph-capturable)
// ---------------------------------------------------------------------------
extern "C" void kernel_launch(void* const* d_in, const int* in_sizes, int n_in,
                              void* d_out, int out_size) {
    const float* x    = (const float*)d_in[0];
    const void*  ei   = d_in[1];
    const float* s0Wl = (const float*)d_in[2];
    const float* s0bl = (const float*)d_in[3];
    const float* s0Wr = (const float*)d_in[4];
    const float* s1Wl = (const float*)d_in[5];
    const float* s1bl = (const float*)d_in[6];
    const float* s1Wr = (const float*)d_in[7];
    const float* l0W  = (const float*)d_in[8];
    const float* l0b  = (const float*)d_in[9];
    const float* l1W  = (const float*)d_in[10];
    const float* l1b  = (const float*)d_in[11];
    float* out = (float*)d_out;

    const int N = in_sizes[0] / D;
    const int E = in_sizes[1] / 2;
    const int NB = (N + SCAN_B - 1) / SCAN_B;

    cudaFuncSetAttribute(sage_mma<0, 0, 1>,
                         cudaFuncAttributeMaxDynamicSharedMemorySize, SM_BYTES);
    cudaFuncSetAttribute(sage_mma<1, 1, 2>,
                         cudaFuncAttributeMaxDynamicSharedMemorySize, SM_BYTES);

    // init (zero + dtype sniff) and weight-plane precompute
    init_kernel<<<(N + 255) / 256, 256>>>((const unsigned int*)ei, 2048, N);
    prep_planes_kernel<<<(4 * KPAIRS * D + 255) / 256, 256>>>(s0Wl, s0Wr,
                                                              s1Wl, s1Wr);
    prep_lin_kernel<<<(64 * 64 + 32 * 8 + 255) / 256, 256>>>(l0W, l1W);

    // CSR build (once per launch; shared by both layers)
    hist_kernel<<<(E + 255) / 256, 256>>>(ei, E, N);
    scan1_kernel<<<NB, SCAN_B>>>(N);
    scan2_kernel<<<1, 32>>>(NB, N, E);
    scan3_kernel<<<NB, SCAN_B>>>(N);
    fill_kernel<<<(E + 255) / 256, 256>>>(ei, E, N);

    const int agg_blocks = (int)(((long long)N * 32 + 255) / 256);
    const int mma_blocks = (N + 127) / 128;

    // layer 0
    agg_kernel<0><<<agg_blocks, 256>>>(x, N);
    sage_mma<0, 0, 1><<<mma_blocks, 256, SM_BYTES>>>(x, s0bl, N);

    // layer 1
    agg_kernel<1><<<agg_blocks, 256>>>(x, N);
    sage_mma<1, 1, 2><<<mma_blocks, 256, SM_BYTES>>>(x, s1bl, N);

    // fused MLP head
    lin_mma<<<mma_blocks, 256>>>(l0b, l1b, out, N);
}

// round 16
// speedup vs baseline: 1.9327x; 1.0547x over previous
#include <cuda_runtime.h>
#include <cuda_bf16.h>
#include <stdint.h>

#define NN 100000
#define NE 600000
#define D 128
#define SCAN_B 1024

#define SM_PITCH 136
#define KPAIRS 64                              // K=128 -> 64 bf16x2 k-pairs
#define SLAB_WORDS (2 * KPAIRS * SM_PITCH)     // hi + lo planes, 17408 words
#define SM_BYTES (SLAB_WORDS * 4)              // 69632 B

// MLP-head slabs
#define L0_PITCH 72
#define L0_WORDS (2 * 64 * L0_PITCH)           // 9216 words (hi+lo)
#define L1_PITCH 8
#define L1_WORDS (2 * 32 * L1_PITCH)           // 512 words

// Scratch (device globals -- no runtime allocation allowed)
__device__ __align__(16) float g_msum[(size_t)NN * D];
__device__ __align__(16) float g_h1[(size_t)NN * D];
__device__ __align__(16) uint32_t g_planes[4 * SLAB_WORDS];  // 4 sage matrices
__device__ __align__(16) uint32_t g_l0planes[L0_WORDS];
__device__ __align__(16) uint32_t g_l1planes[L1_WORDS];
__device__ int g_cnt[NN];
__device__ int g_fill[NN];
__device__ int g_rowptr[NN + 1];
__device__ int g_col[NE];
__device__ int g_blocksum[128];
__device__ int g_blockoff[128];
__device__ int g_is64;

// ---------------------------------------------------------------------------
// bf16 helpers: split f32x2 into bf16x2 hi word + bf16x2 residual word
// ---------------------------------------------------------------------------
__device__ __forceinline__ void split_bf2(float fx, float fy, uint32_t& hi,
                                          uint32_t& lo) {
    __nv_bfloat162 h = __floats2bfloat162_rn(fx, fy);   // .x = fx (low half)
    hi = *(uint32_t*)&h;
    float rx = fx - __bfloat162float(h.x);
    float ry = fy - __bfloat162float(h.y);
    __nv_bfloat162 l = __floats2bfloat162_rn(rx, ry);
    lo = *(uint32_t*)&l;
}

__device__ __forceinline__ void mma_bf16(float& c0, float& c1, float& c2,
                                         float& c3, uint32_t a0, uint32_t a1,
                                         uint32_t a2, uint32_t a3, uint32_t b0,
                                         uint32_t b1) {
    asm("mma.sync.aligned.m16n8k16.row.col.f32.bf16.bf16.f32 "
        "{%0,%1,%2,%3},{%4,%5,%6,%7},{%8,%9},{%0,%1,%2,%3};"
        : "+f"(c0), "+f"(c1), "+f"(c2), "+f"(c3)
        : "r"(a0), "r"(a1), "r"(a2), "r"(a3), "r"(b0), "r"(b1));
}

__device__ __forceinline__ int edge_at(const void* __restrict__ ei, int i) {
    if (g_is64) return (int)((const long long*)ei)[i];
    return ((const int*)ei)[i];
}

// ---------------------------------------------------------------------------
// init: zero cnt/fill arrays; block 0 also sniffs edge-index dtype
// ---------------------------------------------------------------------------
__global__ void init_kernel(const unsigned int* __restrict__ ei32, int npairs,
                            int n) {
    int i = blockIdx.x * blockDim.x + threadIdx.x;
    if (i < n) { g_cnt[i] = 0; g_fill[i] = 0; }
    if (blockIdx.x == 0) {
        __shared__ int any;
        if (threadIdx.x == 0) any = 0;
        __syncthreads();
        int found = 0;
        for (int j = threadIdx.x; j < npairs; j += blockDim.x)
            if (ei32[2 * j + 1] != 0u) found = 1;
        if (found) any = 1;   // benign race
        __syncthreads();
        if (threadIdx.x == 0) g_is64 = (any == 0);
    }
}

// ---------------------------------------------------------------------------
// Precompute bf16 hi/lo weight planes for the sage matrices (SMEM-slab layout).
// Word (kp, n) packs (W[2kp][n], W[2kp+1][n]) as bf16x2.
// ---------------------------------------------------------------------------
__global__ void prep_planes_kernel(const float* __restrict__ Wl0,
                                   const float* __restrict__ Wr0,
                                   const float* __restrict__ Wl1,
                                   const float* __restrict__ Wr1) {
    int idx = blockIdx.x * blockDim.x + threadIdx.x;
    if (idx >= 4 * KPAIRS * D) return;
    int mat = idx >> 13;            // KPAIRS*D = 8192
    int e = idx & 8191;
    int kp = e >> 7, nn = e & 127;
    const float* W = (mat == 0) ? Wl0 : (mat == 1) ? Wr0 : (mat == 2) ? Wl1 : Wr1;
    float f0 = W[(2 * kp) * D + nn];
    float f1 = W[(2 * kp + 1) * D + nn];
    uint32_t hi, lo;
    split_bf2(f0, f1, hi, lo);
    uint32_t* slab = g_planes + mat * SLAB_WORDS;
    slab[kp * SM_PITCH + nn] = hi;
    slab[KPAIRS * SM_PITCH + kp * SM_PITCH + nn] = lo;
}

// ---------------------------------------------------------------------------
// Precompute hi/lo planes for the MLP head (W0 128x64 pitch 72, W1 64x8 pitch 8)
// ---------------------------------------------------------------------------
__global__ void prep_lin_kernel(const float* __restrict__ W0,
                                const float* __restrict__ W1) {
    int idx = blockIdx.x * blockDim.x + threadIdx.x;
    if (idx < 64 * 64) {          // W0: 64 kpairs x 64 cols
        int kp = idx >> 6, nn = idx & 63;
        float f0 = W0[(2 * kp) * 64 + nn];
        float f1 = W0[(2 * kp + 1) * 64 + nn];
        uint32_t hi, lo;
        split_bf2(f0, f1, hi, lo);
        g_l0planes[kp * L0_PITCH + nn] = hi;
        g_l0planes[64 * L0_PITCH + kp * L0_PITCH + nn] = lo;
    }
    int idx1 = idx - 64 * 64;
    if (idx1 >= 0 && idx1 < 32 * 8) {  // W1: 32 kpairs x 8 cols
        int kp = idx1 >> 3, nn = idx1 & 7;
        float f0 = W1[(2 * kp) * 8 + nn];
        float f1 = W1[(2 * kp + 1) * 8 + nn];
        uint32_t hi, lo;
        split_bf2(f0, f1, hi, lo);
        g_l1planes[kp * L1_PITCH + nn] = hi;
        g_l1planes[32 * L1_PITCH + kp * L1_PITCH + nn] = lo;
    }
}

// ---------------------------------------------------------------------------
// CSR build: histogram -> block scan -> fill
// ---------------------------------------------------------------------------
__global__ void hist_kernel(const void* __restrict__ ei, int E, int n) {
    int e = blockIdx.x * blockDim.x + threadIdx.x;
    if (e >= E) return;
    unsigned d = min((unsigned)edge_at(ei, E + e), (unsigned)(n - 1));
    atomicAdd(&g_cnt[d], 1);
}

__global__ void __launch_bounds__(SCAN_B) scan1_kernel(int n) {
    __shared__ int sm[SCAN_B];
    int i = blockIdx.x * SCAN_B + threadIdx.x;
    sm[threadIdx.x] = (i < n) ? g_cnt[i] : 0;
    __syncthreads();
    for (int off = SCAN_B / 2; off > 0; off >>= 1) {
        if (threadIdx.x < off) sm[threadIdx.x] += sm[threadIdx.x + off];
        __syncthreads();
    }
    if (threadIdx.x == 0) g_blocksum[blockIdx.x] = sm[0];
}

__global__ void scan2_kernel(int nb, int n, int E) {
    if (threadIdx.x == 0) {
        int run = 0;
        for (int b = 0; b < nb; b++) { g_blockoff[b] = run; run += g_blocksum[b]; }
        g_rowptr[n] = E;
    }
}

__global__ void __launch_bounds__(SCAN_B) scan3_kernel(int n) {
    __shared__ int sm[SCAN_B];
    int i = blockIdx.x * SCAN_B + threadIdx.x;
    int v = (i < n) ? g_cnt[i] : 0;
    sm[threadIdx.x] = v;
    __syncthreads();
    for (int off = 1; off < SCAN_B; off <<= 1) {
        int t = 0;
        if ((int)threadIdx.x >= off) t = sm[threadIdx.x - off];
        __syncthreads();
        if ((int)threadIdx.x >= off) sm[threadIdx.x] += t;
        __syncthreads();
    }
    if (i < n) g_rowptr[i] = g_blockoff[blockIdx.x] + sm[threadIdx.x] - v;
}

__global__ void fill_kernel(const void* __restrict__ ei, int E, int n) {
    int e = blockIdx.x * blockDim.x + threadIdx.x;
    if (e >= E) return;
    unsigned s = min((unsigned)edge_at(ei, e), (unsigned)(n - 1));
    unsigned d = min((unsigned)edge_at(ei, E + e), (unsigned)(n - 1));
    int pos = g_rowptr[d] + atomicAdd(&g_fill[d], 1);
    g_col[pos] = (int)s;
}

// ---------------------------------------------------------------------------
// Gather aggregation: msum[i] = mean over in-neighbors of h[col].
// ---------------------------------------------------------------------------
template <int SRC>
__global__ void __launch_bounds__(256) agg_kernel(const float* __restrict__ x,
                                                  int n) {
    int tid = blockIdx.x * blockDim.x + threadIdx.x;
    int node = tid >> 5;
    if (node >= n) return;
    int lane = tid & 31;
    const float* h = (SRC == 0) ? x : g_h1;
    int beg = g_rowptr[node], end = g_rowptr[node + 1];
    float4 acc = make_float4(0.f, 0.f, 0.f, 0.f);
    int k = beg;
    for (; k + 4 <= end; k += 4) {
        int c0 = g_col[k + 0], c1 = g_col[k + 1];
        int c2 = g_col[k + 2], c3 = g_col[k + 3];
        float4 v0 = *(const float4*)(h + (size_t)c0 * D + lane * 4);
        float4 v1 = *(const float4*)(h + (size_t)c1 * D + lane * 4);
        float4 v2 = *(const float4*)(h + (size_t)c2 * D + lane * 4);
        float4 v3 = *(const float4*)(h + (size_t)c3 * D + lane * 4);
        acc.x += v0.x + v1.x + v2.x + v3.x;
        acc.y += v0.y + v1.y + v2.y + v3.y;
        acc.z += v0.z + v1.z + v2.z + v3.z;
        acc.w += v0.w + v1.w + v2.w + v3.w;
    }
    for (; k < end; ++k) {
        int c = g_col[k];
        float4 v = *(const float4*)(h + (size_t)c * D + lane * 4);
        acc.x += v.x; acc.y += v.y; acc.z += v.z; acc.w += v.w;
    }
    float sc = 1.f / fmaxf((float)(end - beg), 1.f);
    acc.x *= sc; acc.y *= sc; acc.z *= sc; acc.w *= sc;
    *(float4*)(g_msum + (size_t)node * D + lane * 4) = acc;
}

// ---------------------------------------------------------------------------
// SAGE layer via tensor cores (3x-split BF16, m16n8k16):
//   h_out = relu(msum@Wl + bl + h@Wr)
// HEAD=0: write h_out rows to g_h1.
// HEAD=1 (layer 1): do NOT write h2; instead fuse the full MLP head:
//   out[row, 0..7] = relu( relu(h2@W0+b0) @ W1 + b1 )
// using the C-fragment == A-fragment layout identity twice (h2 and t never
// leave registers).
// ---------------------------------------------------------------------------
template <int LAYER, int SRC, int HEAD>
__global__ void __launch_bounds__(256, 2) sage_mma(
    const float* __restrict__ x, const float* __restrict__ bl,
    const float* __restrict__ b0v, const float* __restrict__ b1v,
    float* __restrict__ outp, int n) {
    extern __shared__ uint32_t sw[];
    uint32_t* sWhi = sw;
    uint32_t* sWlo = sw + KPAIRS * SM_PITCH;

    const int tid = threadIdx.x;
    const int wid = tid >> 5;
    const int lane = tid & 31;
    const int g = lane >> 2;     // group id: row within tile
    const int tig = lane & 3;    // thread in group

    const float* h = (SRC == 0) ? x : g_h1;

    const int wbase = blockIdx.x * 128 + wid * 16;
    const int r0 = min(wbase + g, n - 1);
    const int r1 = min(wbase + g + 8, n - 1);

    float c[16][4];
#pragma unroll
    for (int nt = 0; nt < 16; ++nt) {
        int col0 = nt * 8 + tig * 2;
        float b0 = bl[col0], b1 = bl[col0 + 1];
        c[nt][0] = b0; c[nt][1] = b1;
        c[nt][2] = b0; c[nt][3] = b1;
    }

#pragma unroll 1
    for (int pass = 0; pass < 2; ++pass) {
        const uint32_t* slab = g_planes + (LAYER * 2 + pass) * SLAB_WORDS;
        const float* A = (pass == 0) ? g_msum : h;

        __syncthreads();
        {
            const float4* src4 = (const float4*)slab;
            float4* dst4 = (float4*)sw;
            for (int idx = tid; idx < SLAB_WORDS / 4; idx += 256)
                dst4[idx] = src4[idx];
        }
        __syncthreads();

        const float* a0p = A + (size_t)r0 * D;
        const float* a1p = A + (size_t)r1 * D;

#pragma unroll
        for (int ks = 0; ks < 8; ++ks) {
            const int kc = ks * 16 + tig * 2;
            float2 f0 = *(const float2*)(a0p + kc);
            float2 f1 = *(const float2*)(a1p + kc);
            float2 f2v = *(const float2*)(a0p + kc + 8);
            float2 f3 = *(const float2*)(a1p + kc + 8);
            uint32_t ah0, al0, ah1, al1, ah2, al2, ah3, al3;
            split_bf2(f0.x, f0.y, ah0, al0);
            split_bf2(f1.x, f1.y, ah1, al1);
            split_bf2(f2v.x, f2v.y, ah2, al2);
            split_bf2(f3.x, f3.y, ah3, al3);

            const int kb = (ks * 8 + tig) * SM_PITCH + g;
#pragma unroll
            for (int nt = 0; nt < 16; ++nt) {
                const int base = kb + nt * 8;
                uint32_t bh0 = sWhi[base];
                uint32_t bh1 = sWhi[base + 4 * SM_PITCH];
                uint32_t bl0 = sWlo[base];
                uint32_t bl1 = sWlo[base + 4 * SM_PITCH];
                mma_bf16(c[nt][0], c[nt][1], c[nt][2], c[nt][3],
                         ah0, ah1, ah2, ah3, bh0, bh1);
                mma_bf16(c[nt][0], c[nt][1], c[nt][2], c[nt][3],
                         ah0, ah1, ah2, ah3, bl0, bl1);
                mma_bf16(c[nt][0], c[nt][1], c[nt][2], c[nt][3],
                         al0, al1, al2, al3, bh0, bh1);
            }
        }
    }

    const int row0 = wbase + g;
    const int row1 = wbase + g + 8;

    if (HEAD == 0) {
        // epilogue: relu + store feature rows to g_h1
        if (row0 < n) {
            float* o = g_h1 + (size_t)row0 * D + tig * 2;
#pragma unroll
            for (int nt = 0; nt < 16; ++nt)
                *(float2*)(o + nt * 8) =
                    make_float2(fmaxf(c[nt][0], 0.f), fmaxf(c[nt][1], 0.f));
        }
        if (row1 < n) {
            float* o = g_h1 + (size_t)row1 * D + tig * 2;
#pragma unroll
            for (int nt = 0; nt < 16; ++nt)
                *(float2*)(o + nt * 8) =
                    make_float2(fmaxf(c[nt][2], 0.f), fmaxf(c[nt][3], 0.f));
        }
        return;
    }

    // ---- fused MLP head (layer 1): h2 = relu(c) lives in registers ----
    __syncthreads();   // mainloop LDS reads done; reuse SMEM for W0/W1 slabs
    {
        const float4* src0 = (const float4*)g_l0planes;
        float4* dst0 = (float4*)sw;
        for (int idx = tid; idx < L0_WORDS / 4; idx += 256) dst0[idx] = src0[idx];
        const float4* src1 = (const float4*)g_l1planes;
        float4* dst1 = (float4*)(sw + L0_WORDS);
        for (int idx = tid; idx < L1_WORDS / 4; idx += 256) dst1[idx] = src1[idx];
    }
    __syncthreads();

    const uint32_t* s0hi = sw;
    const uint32_t* s0lo = sw + 64 * L0_PITCH;
    const uint32_t* s1hi = sw + L0_WORDS;
    const uint32_t* s1lo = sw + L0_WORDS + 32 * L1_PITCH;

    // GEMM 1: t = relu(h2) @ W0 + b0  (64 cols = 8 n-tiles, K=128)
    float t[8][4];
#pragma unroll
    for (int nt = 0; nt < 8; ++nt) {
        int col0 = nt * 8 + tig * 2;
        float b0 = b0v[col0], b1 = b0v[col0 + 1];
        t[nt][0] = b0; t[nt][1] = b1;
        t[nt][2] = b0; t[nt][3] = b1;
    }

#pragma unroll
    for (int j = 0; j < 8; ++j) {   // k-chunks of 16 over K=128
        uint32_t ah0, al0, ah1, al1, ah2, al2, ah3, al3;
        split_bf2(fmaxf(c[2 * j][0], 0.f), fmaxf(c[2 * j][1], 0.f), ah0, al0);
        split_bf2(fmaxf(c[2 * j][2], 0.f), fmaxf(c[2 * j][3], 0.f), ah1, al1);
        split_bf2(fmaxf(c[2 * j + 1][0], 0.f), fmaxf(c[2 * j + 1][1], 0.f),
                  ah2, al2);
        split_bf2(fmaxf(c[2 * j + 1][2], 0.f), fmaxf(c[2 * j + 1][3], 0.f),
                  ah3, al3);

        const int kb = (j * 8 + tig) * L0_PITCH + g;
#pragma unroll
        for (int nt = 0; nt < 8; ++nt) {
            const int base = kb + nt * 8;
            uint32_t bh0 = s0hi[base];
            uint32_t bh1 = s0hi[base + 4 * L0_PITCH];
            uint32_t bl0 = s0lo[base];
            uint32_t bl1 = s0lo[base + 4 * L0_PITCH];
            mma_bf16(t[nt][0], t[nt][1], t[nt][2], t[nt][3],
                     ah0, ah1, ah2, ah3, bh0, bh1);
            mma_bf16(t[nt][0], t[nt][1], t[nt][2], t[nt][3],
                     ah0, ah1, ah2, ah3, bl0, bl1);
            mma_bf16(t[nt][0], t[nt][1], t[nt][2], t[nt][3],
                     al0, al1, al2, al3, bh0, bh1);
        }
    }

    // GEMM 2: o = relu(t) @ W1 + b1  (8 cols = 1 n-tile, K=64)
    float o[4];
    {
        float b0 = b1v[tig * 2], b1 = b1v[tig * 2 + 1];
        o[0] = b0; o[1] = b1; o[2] = b0; o[3] = b1;
    }

#pragma unroll
    for (int j = 0; j < 4; ++j) {   // k-chunks of 16 over K=64
        uint32_t ah0, al0, ah1, al1, ah2, al2, ah3, al3;
        split_bf2(fmaxf(t[2 * j][0], 0.f), fmaxf(t[2 * j][1], 0.f), ah0, al0);
        split_bf2(fmaxf(t[2 * j][2], 0.f), fmaxf(t[2 * j][3], 0.f), ah1, al1);
        split_bf2(fmaxf(t[2 * j + 1][0], 0.f), fmaxf(t[2 * j + 1][1], 0.f),
                  ah2, al2);
        split_bf2(fmaxf(t[2 * j + 1][2], 0.f), fmaxf(t[2 * j + 1][3], 0.f),
                  ah3, al3);

        const int kb = (j * 8 + tig) * L1_PITCH + g;
        uint32_t bh0 = s1hi[kb];
        uint32_t bh1 = s1hi[kb + 4 * L1_PITCH];
        uint32_t bl0 = s1lo[kb];
        uint32_t bl1 = s1lo[kb + 4 * L1_PITCH];
        mma_bf16(o[0], o[1], o[2], o[3], ah0, ah1, ah2, ah3, bh0, bh1);
        mma_bf16(o[0], o[1], o[2], o[3], ah0, ah1, ah2, ah3, bl0, bl1);
        mma_bf16(o[0], o[1], o[2], o[3], al0, al1, al2, al3, bh0, bh1);
    }

    if (row0 < n)
        *(float2*)(outp + (size_t)row0 * 8 + tig * 2) =
            make_float2(fmaxf(o[0], 0.f), fmaxf(o[1], 0.f));
    if (row1 < n)
        *(float2*)(outp + (size_t)row1 * 8 + tig * 2) =
            make_float2(fmaxf(o[2], 0.f), fmaxf(o[3], 0.f));
}

// ---------------------------------------------------------------------------
// Launcher (no allocation, graph-capturable)
// ---------------------------------------------------------------------------
extern "C" void kernel_launch(void* const* d_in, const int* in_sizes, int n_in,
                              void* d_out, int out_size) {
    const float* x    = (const float*)d_in[0];
    const void*  ei   = d_in[1];
    const float* s0Wl = (const float*)d_in[2];
    const float* s0bl = (const float*)d_in[3];
    const float* s0Wr = (const float*)d_in[4];
    const float* s1Wl = (const float*)d_in[5];
    const float* s1bl = (const float*)d_in[6];
    const float* s1Wr = (const float*)d_in[7];
    const float* l0W  = (const float*)d_in[8];
    const float* l0b  = (const float*)d_in[9];
    const float* l1W  = (const float*)d_in[10];
    const float* l1b  = (const float*)d_in[11];
    float* out = (float*)d_out;

    const int N = in_sizes[0] / D;
    const int E = in_sizes[1] / 2;
    const int NB = (N + SCAN_B - 1) / SCAN_B;

    cudaFuncSetAttribute(sage_mma<0, 0, 0>,
                         cudaFuncAttributeMaxDynamicSharedMemorySize, SM_BYTES);
    cudaFuncSetAttribute(sage_mma<1, 1, 1>,
                         cudaFuncAttributeMaxDynamicSharedMemorySize, SM_BYTES);

    // init (zero + dtype sniff) and weight-plane precompute
    init_kernel<<<(N + 255) / 256, 256>>>((const unsigned int*)ei, 2048, N);
    prep_planes_kernel<<<(4 * KPAIRS * D + 255) / 256, 256>>>(s0Wl, s0Wr,
                                                              s1Wl, s1Wr);
    prep_lin_kernel<<<(64 * 64 + 32 * 8 + 255) / 256, 256>>>(l0W, l1W);

    // CSR build (once per launch; shared by both layers)
    hist_kernel<<<(E + 255) / 256, 256>>>(ei, E, N);
    scan1_kernel<<<NB, SCAN_B>>>(N);
    scan2_kernel<<<1, 32>>>(NB, N, E);
    scan3_kernel<<<NB, SCAN_B>>>(N);
    fill_kernel<<<(E + 255) / 256, 256>>>(ei, E, N);

    const int agg_blocks = (int)(((long long)N * 32 + 255) / 256);
    const int mma_blocks = (N + 127) / 128;

    // layer 0: agg(x) -> msum; sage -> g_h1
    agg_kernel<0><<<agg_blocks, 256>>>(x, N);
    sage_mma<0, 0, 0><<<mma_blocks, 256, SM_BYTES>>>(x, s0bl, nullptr, nullptr,
                                                     nullptr, N);

    // layer 1 + fused MLP head: agg(h1) -> msum; sage + head -> out
    agg_kernel<1><<<agg_blocks, 256>>>(x, N);
    sage_mma<1, 1, 1><<<mma_blocks, 256, SM_BYTES>>>(x, s1bl, l0b, l1b, out, N);
}

// round 17
// speedup vs baseline: 1.9699x; 1.0193x over previous
#include <cuda_runtime.h>
#include <cuda_bf16.h>
#include <stdint.h>

#define NN 100000
#define NE 600000
#define D 128
#define SCAN_B 1024

#define SM_PITCH 136
#define KPAIRS 64                              // K=128 -> 64 bf16x2 k-pairs
#define SLAB_WORDS (2 * KPAIRS * SM_PITCH)     // hi + lo planes, 17408 words
#define SM_BYTES (SLAB_WORDS * 4)              // 69632 B

// MLP-head slabs
#define L0_PITCH 72
#define L0_WORDS (2 * 64 * L0_PITCH)           // 9216 words (hi+lo)
#define L1_PITCH 8
#define L1_WORDS (2 * 32 * L1_PITCH)           // 512 words

// Scratch (device globals -- no runtime allocation allowed)
__device__ __align__(16) float g_msum[(size_t)NN * D];
__device__ __align__(16) float g_h1[(size_t)NN * D];
__device__ __align__(16) uint32_t g_planes[4 * SLAB_WORDS];  // 4 sage matrices
__device__ __align__(16) uint32_t g_l0planes[L0_WORDS];
__device__ __align__(16) uint32_t g_l1planes[L1_WORDS];
__device__ int g_cnt[NN];
__device__ int g_fill[NN];
__device__ int g_rowptr[NN + 1];
__device__ int g_col[NE];
__device__ int g_blocksum[128];
__device__ int g_blockoff[128];
__device__ int g_ticket;
__device__ int g_is64;

// ---------------------------------------------------------------------------
// bf16 helpers: split f32x2 into bf16x2 hi word + bf16x2 residual word
// ---------------------------------------------------------------------------
__device__ __forceinline__ void split_bf2(float fx, float fy, uint32_t& hi,
                                          uint32_t& lo) {
    __nv_bfloat162 h = __floats2bfloat162_rn(fx, fy);   // .x = fx (low half)
    hi = *(uint32_t*)&h;
    float rx = fx - __bfloat162float(h.x);
    float ry = fy - __bfloat162float(h.y);
    __nv_bfloat162 l = __floats2bfloat162_rn(rx, ry);
    lo = *(uint32_t*)&l;
}

__device__ __forceinline__ void mma_bf16(float& c0, float& c1, float& c2,
                                         float& c3, uint32_t a0, uint32_t a1,
                                         uint32_t a2, uint32_t a3, uint32_t b0,
                                         uint32_t b1) {
    asm("mma.sync.aligned.m16n8k16.row.col.f32.bf16.bf16.f32 "
        "{%0,%1,%2,%3},{%4,%5,%6,%7},{%8,%9},{%0,%1,%2,%3};"
        : "+f"(c0), "+f"(c1), "+f"(c2), "+f"(c3)
        : "r"(a0), "r"(a1), "r"(a2), "r"(a3), "r"(b0), "r"(b1));
}

__device__ __forceinline__ int edge_at(const void* __restrict__ ei, int i) {
    if (g_is64) return (int)((const long long*)ei)[i];
    return ((const int*)ei)[i];
}

// ---------------------------------------------------------------------------
// setup: zero cnt/fill + ticket, dtype sniff (block 0), and bf16 hi/lo
// weight-plane precompute for sage matrices AND MLP head. All index ranges
// disjoint and independent of edge data (except the sniff).
// ---------------------------------------------------------------------------
__global__ void setup_kernel(const unsigned int* __restrict__ ei32, int npairs,
                             int n,
                             const float* __restrict__ Wl0,
                             const float* __restrict__ Wr0,
                             const float* __restrict__ Wl1,
                             const float* __restrict__ Wr1,
                             const float* __restrict__ W0,
                             const float* __restrict__ W1) {
    int i = blockIdx.x * blockDim.x + threadIdx.x;
    if (i < n) { g_cnt[i] = 0; g_fill[i] = 0; }
    if (i == 0) g_ticket = 0;

    // sage weight planes: 4 matrices x (KPAIRS x D) words
    if (i < 4 * KPAIRS * D) {
        int mat = i >> 13;            // KPAIRS*D = 8192
        int e = i & 8191;
        int kp = e >> 7, nn = e & 127;
        const float* W = (mat == 0) ? Wl0 : (mat == 1) ? Wr0
                                          : (mat == 2) ? Wl1 : Wr1;
        float f0 = W[(2 * kp) * D + nn];
        float f1 = W[(2 * kp + 1) * D + nn];
        uint32_t hi, lo;
        split_bf2(f0, f1, hi, lo);
        uint32_t* slab = g_planes + mat * SLAB_WORDS;
        slab[kp * SM_PITCH + nn] = hi;
        slab[KPAIRS * SM_PITCH + kp * SM_PITCH + nn] = lo;
    }
    // MLP-head planes
    if (i < 64 * 64) {                // W0: 64 kpairs x 64 cols
        int kp = i >> 6, nn = i & 63;
        float f0 = W0[(2 * kp) * 64 + nn];
        float f1 = W0[(2 * kp + 1) * 64 + nn];
        uint32_t hi, lo;
        split_bf2(f0, f1, hi, lo);
        g_l0planes[kp * L0_PITCH + nn] = hi;
        g_l0planes[64 * L0_PITCH + kp * L0_PITCH + nn] = lo;
    }
    {
        int i1 = i - 64 * 64;
        if (i1 >= 0 && i1 < 32 * 8) { // W1: 32 kpairs x 8 cols
            int kp = i1 >> 3, nn = i1 & 7;
            float f0 = W1[(2 * kp) * 8 + nn];
            float f1 = W1[(2 * kp + 1) * 8 + nn];
            uint32_t hi, lo;
            split_bf2(f0, f1, hi, lo);
            g_l1planes[kp * L1_PITCH + nn] = hi;
            g_l1planes[32 * L1_PITCH + kp * L1_PITCH + nn] = lo;
        }
    }

    if (blockIdx.x == 0) {
        __shared__ int any;
        if (threadIdx.x == 0) any = 0;
        __syncthreads();
        int found = 0;
        for (int j = threadIdx.x; j < npairs; j += blockDim.x)
            if (ei32[2 * j + 1] != 0u) found = 1;
        if (found) any = 1;   // benign race
        __syncthreads();
        if (threadIdx.x == 0) g_is64 = (any == 0);
    }
}

// ---------------------------------------------------------------------------
// CSR build: histogram -> (block sums + last-block offsets) -> scan3 -> fill
// ---------------------------------------------------------------------------
__global__ void hist_kernel(const void* __restrict__ ei, int E, int n) {
    int e = blockIdx.x * blockDim.x + threadIdx.x;
    if (e >= E) return;
    unsigned d = min((unsigned)edge_at(ei, E + e), (unsigned)(n - 1));
    atomicAdd(&g_cnt[d], 1);
}

// scan1: per-block sums; the LAST arriving block serially computes offsets
__global__ void __launch_bounds__(SCAN_B) scan1_kernel(int n, int nb, int E) {
    __shared__ int sm[SCAN_B];
    int i = blockIdx.x * SCAN_B + threadIdx.x;
    sm[threadIdx.x] = (i < n) ? g_cnt[i] : 0;
    __syncthreads();
    for (int off = SCAN_B / 2; off > 0; off >>= 1) {
        if (threadIdx.x < off) sm[threadIdx.x] += sm[threadIdx.x + off];
        __syncthreads();
    }
    if (threadIdx.x == 0) {
        g_blocksum[blockIdx.x] = sm[0];
        __threadfence();
        int t = atomicAdd(&g_ticket, 1);
        if (t == nb - 1) {   // all block sums visible
            int run = 0;
            for (int b = 0; b < nb; b++) {
                g_blockoff[b] = run;
                run += g_blocksum[b];
            }
            g_rowptr[n] = E;
        }
    }
}

__global__ void __launch_bounds__(SCAN_B) scan3_kernel(int n) {
    __shared__ int sm[SCAN_B];
    int i = blockIdx.x * SCAN_B + threadIdx.x;
    int v = (i < n) ? g_cnt[i] : 0;
    sm[threadIdx.x] = v;
    __syncthreads();
    for (int off = 1; off < SCAN_B; off <<= 1) {
        int t = 0;
        if ((int)threadIdx.x >= off) t = sm[threadIdx.x - off];
        __syncthreads();
        if ((int)threadIdx.x >= off) sm[threadIdx.x] += t;
        __syncthreads();
    }
    if (i < n) g_rowptr[i] = g_blockoff[blockIdx.x] + sm[threadIdx.x] - v;
}

__global__ void fill_kernel(const void* __restrict__ ei, int E, int n) {
    int e = blockIdx.x * blockDim.x + threadIdx.x;
    if (e >= E) return;
    unsigned s = min((unsigned)edge_at(ei, e), (unsigned)(n - 1));
    unsigned d = min((unsigned)edge_at(ei, E + e), (unsigned)(n - 1));
    int pos = g_rowptr[d] + atomicAdd(&g_fill[d], 1);
    g_col[pos] = (int)s;
}

// ---------------------------------------------------------------------------
// Gather aggregation: msum[i] = mean over in-neighbors of h[col].
// ---------------------------------------------------------------------------
template <int SRC>
__global__ void __launch_bounds__(256) agg_kernel(const float* __restrict__ x,
                                                  int n) {
    int tid = blockIdx.x * blockDim.x + threadIdx.x;
    int node = tid >> 5;
    if (node >= n) return;
    int lane = tid & 31;
    const float* h = (SRC == 0) ? x : g_h1;
    int beg = g_rowptr[node], end = g_rowptr[node + 1];
    float4 acc = make_float4(0.f, 0.f, 0.f, 0.f);
    int k = beg;
    for (; k + 4 <= end; k += 4) {
        int c0 = g_col[k + 0], c1 = g_col[k + 1];
        int c2 = g_col[k + 2], c3 = g_col[k + 3];
        float4 v0 = *(const float4*)(h + (size_t)c0 * D + lane * 4);
        float4 v1 = *(const float4*)(h + (size_t)c1 * D + lane * 4);
        float4 v2 = *(const float4*)(h + (size_t)c2 * D + lane * 4);
        float4 v3 = *(const float4*)(h + (size_t)c3 * D + lane * 4);
        acc.x += v0.x + v1.x + v2.x + v3.x;
        acc.y += v0.y + v1.y + v2.y + v3.y;
        acc.z += v0.z + v1.z + v2.z + v3.z;
        acc.w += v0.w + v1.w + v2.w + v3.w;
    }
    for (; k < end; ++k) {
        int c = g_col[k];
        float4 v = *(const float4*)(h + (size_t)c * D + lane * 4);
        acc.x += v.x; acc.y += v.y; acc.z += v.z; acc.w += v.w;
    }
    float sc = 1.f / fmaxf((float)(end - beg), 1.f);
    acc.x *= sc; acc.y *= sc; acc.z *= sc; acc.w *= sc;
    *(float4*)(g_msum + (size_t)node * D + lane * 4) = acc;
}

// ---------------------------------------------------------------------------
// SAGE layer via tensor cores (3x-split BF16, m16n8k16):
//   h_out = relu(msum@Wl + bl + h@Wr)
// HEAD=0: write h_out rows to g_h1.
// HEAD=1 (layer 1): fuse the full MLP head in the epilogue; h2 and t stay in
// registers via the C-fragment == A-fragment layout identity.
// ---------------------------------------------------------------------------
template <int LAYER, int SRC, int HEAD>
__global__ void __launch_bounds__(256, 2) sage_mma(
    const float* __restrict__ x, const float* __restrict__ bl,
    const float* __restrict__ b0v, const float* __restrict__ b1v,
    float* __restrict__ outp, int n) {
    extern __shared__ uint32_t sw[];
    uint32_t* sWhi = sw;
    uint32_t* sWlo = sw + KPAIRS * SM_PITCH;

    const int tid = threadIdx.x;
    const int wid = tid >> 5;
    const int lane = tid & 31;
    const int g = lane >> 2;     // group id: row within tile
    const int tig = lane & 3;    // thread in group

    const float* h = (SRC == 0) ? x : g_h1;

    const int wbase = blockIdx.x * 128 + wid * 16;
    const int r0 = min(wbase + g, n - 1);
    const int r1 = min(wbase + g + 8, n - 1);

    float c[16][4];
#pragma unroll
    for (int nt = 0; nt < 16; ++nt) {
        int col0 = nt * 8 + tig * 2;
        float b0 = bl[col0], b1 = bl[col0 + 1];
        c[nt][0] = b0; c[nt][1] = b1;
        c[nt][2] = b0; c[nt][3] = b1;
    }

#pragma unroll 1
    for (int pass = 0; pass < 2; ++pass) {
        const uint32_t* slab = g_planes + (LAYER * 2 + pass) * SLAB_WORDS;
        const float* A = (pass == 0) ? g_msum : h;

        __syncthreads();
        {
            const float4* src4 = (const float4*)slab;
            float4* dst4 = (float4*)sw;
            for (int idx = tid; idx < SLAB_WORDS / 4; idx += 256)
                dst4[idx] = src4[idx];
        }
        __syncthreads();

        const float* a0p = A + (size_t)r0 * D;
        const float* a1p = A + (size_t)r1 * D;

#pragma unroll
        for (int ks = 0; ks < 8; ++ks) {
            const int kc = ks * 16 + tig * 2;
            float2 f0 = *(const float2*)(a0p + kc);
            float2 f1 = *(const float2*)(a1p + kc);
            float2 f2v = *(const float2*)(a0p + kc + 8);
            float2 f3 = *(const float2*)(a1p + kc + 8);
            uint32_t ah0, al0, ah1, al1, ah2, al2, ah3, al3;
            split_bf2(f0.x, f0.y, ah0, al0);
            split_bf2(f1.x, f1.y, ah1, al1);
            split_bf2(f2v.x, f2v.y, ah2, al2);
            split_bf2(f3.x, f3.y, ah3, al3);

            const int kb = (ks * 8 + tig) * SM_PITCH + g;
#pragma unroll
            for (int nt = 0; nt < 16; ++nt) {
                const int base = kb + nt * 8;
                uint32_t bh0 = sWhi[base];
                uint32_t bh1 = sWhi[base + 4 * SM_PITCH];
                uint32_t bl0 = sWlo[base];
                uint32_t bl1 = sWlo[base + 4 * SM_PITCH];
                mma_bf16(c[nt][0], c[nt][1], c[nt][2], c[nt][3],
                         ah0, ah1, ah2, ah3, bh0, bh1);
                mma_bf16(c[nt][0], c[nt][1], c[nt][2], c[nt][3],
                         ah0, ah1, ah2, ah3, bl0, bl1);
                mma_bf16(c[nt][0], c[nt][1], c[nt][2], c[nt][3],
                         al0, al1, al2, al3, bh0, bh1);
            }
        }
    }

    const int row0 = wbase + g;
    const int row1 = wbase + g + 8;

    if (HEAD == 0) {
        if (row0 < n) {
            float* o = g_h1 + (size_t)row0 * D + tig * 2;
#pragma unroll
            for (int nt = 0; nt < 16; ++nt)
                *(float2*)(o + nt * 8) =
                    make_float2(fmaxf(c[nt][0], 0.f), fmaxf(c[nt][1], 0.f));
        }
        if (row1 < n) {
            float* o = g_h1 + (size_t)row1 * D + tig * 2;
#pragma unroll
            for (int nt = 0; nt < 16; ++nt)
                *(float2*)(o + nt * 8) =
                    make_float2(fmaxf(c[nt][2], 0.f), fmaxf(c[nt][3], 0.f));
        }
        return;
    }

    // ---- fused MLP head (layer 1): h2 = relu(c) lives in registers ----
    __syncthreads();   // mainloop LDS reads done; reuse SMEM for W0/W1 slabs
    {
        const float4* src0 = (const float4*)g_l0planes;
        float4* dst0 = (float4*)sw;
        for (int idx = tid; idx < L0_WORDS / 4; idx += 256) dst0[idx] = src0[idx];
        const float4* src1 = (const float4*)g_l1planes;
        float4* dst1 = (float4*)(sw + L0_WORDS);
        for (int idx = tid; idx < L1_WORDS / 4; idx += 256) dst1[idx] = src1[idx];
    }
    __syncthreads();

    const uint32_t* s0hi = sw;
    const uint32_t* s0lo = sw + 64 * L0_PITCH;
    const uint32_t* s1hi = sw + L0_WORDS;
    const uint32_t* s1lo = sw + L0_WORDS + 32 * L1_PITCH;

    // GEMM 1: t = relu(h2) @ W0 + b0  (64 cols = 8 n-tiles, K=128)
    float t[8][4];
#pragma unroll
    for (int nt = 0; nt < 8; ++nt) {
        int col0 = nt * 8 + tig * 2;
        float b0 = b0v[col0], b1 = b0v[col0 + 1];
        t[nt][0] = b0; t[nt][1] = b1;
        t[nt][2] = b0; t[nt][3] = b1;
    }

#pragma unroll
    for (int j = 0; j < 8; ++j) {   // k-chunks of 16 over K=128
        uint32_t ah0, al0, ah1, al1, ah2, al2, ah3, al3;
        split_bf2(fmaxf(c[2 * j][0], 0.f), fmaxf(c[2 * j][1], 0.f), ah0, al0);
        split_bf2(fmaxf(c[2 * j][2], 0.f), fmaxf(c[2 * j][3], 0.f), ah1, al1);
        split_bf2(fmaxf(c[2 * j + 1][0], 0.f), fmaxf(c[2 * j + 1][1], 0.f),
                  ah2, al2);
        split_bf2(fmaxf(c[2 * j + 1][2], 0.f), fmaxf(c[2 * j + 1][3], 0.f),
                  ah3, al3);

        const int kb = (j * 8 + tig) * L0_PITCH + g;
#pragma unroll
        for (int nt = 0; nt < 8; ++nt) {
            const int base = kb + nt * 8;
            uint32_t bh0 = s0hi[base];
            uint32_t bh1 = s0hi[base + 4 * L0_PITCH];
            uint32_t bl0 = s0lo[base];
            uint32_t bl1 = s0lo[base + 4 * L0_PITCH];
            mma_bf16(t[nt][0], t[nt][1], t[nt][2], t[nt][3],
                     ah0, ah1, ah2, ah3, bh0, bh1);
            mma_bf16(t[nt][0], t[nt][1], t[nt][2], t[nt][3],
                     ah0, ah1, ah2, ah3, bl0, bl1);
            mma_bf16(t[nt][0], t[nt][1], t[nt][2], t[nt][3],
                     al0, al1, al2, al3, bh0, bh1);
        }
    }

    // GEMM 2: o = relu(t) @ W1 + b1  (8 cols = 1 n-tile, K=64)
    float o[4];
    {
        float b0 = b1v[tig * 2], b1 = b1v[tig * 2 + 1];
        o[0] = b0; o[1] = b1; o[2] = b0; o[3] = b1;
    }

#pragma unroll
    for (int j = 0; j < 4; ++j) {   // k-chunks of 16 over K=64
        uint32_t ah0, al0, ah1, al1, ah2, al2, ah3, al3;
        split_bf2(fmaxf(t[2 * j][0], 0.f), fmaxf(t[2 * j][1], 0.f), ah0, al0);
        split_bf2(fmaxf(t[2 * j][2], 0.f), fmaxf(t[2 * j][3], 0.f), ah1, al1);
        split_bf2(fmaxf(t[2 * j + 1][0], 0.f), fmaxf(t[2 * j + 1][1], 0.f),
                  ah2, al2);
        split_bf2(fmaxf(t[2 * j + 1][2], 0.f), fmaxf(t[2 * j + 1][3], 0.f),
                  ah3, al3);

        const int kb = (j * 8 + tig) * L1_PITCH + g;
        uint32_t bh0 = s1hi[kb];
        uint32_t bh1 = s1hi[kb + 4 * L1_PITCH];
        uint32_t bl0 = s1lo[kb];
        uint32_t bl1 = s1lo[kb + 4 * L1_PITCH];
        mma_bf16(o[0], o[1], o[2], o[3], ah0, ah1, ah2, ah3, bh0, bh1);
        mma_bf16(o[0], o[1], o[2], o[3], ah0, ah1, ah2, ah3, bl0, bl1);
        mma_bf16(o[0], o[1], o[2], o[3], al0, al1, al2, al3, bh0, bh1);
    }

    if (row0 < n)
        *(float2*)(outp + (size_t)row0 * 8 + tig * 2) =
            make_float2(fmaxf(o[0], 0.f), fmaxf(o[1], 0.f));
    if (row1 < n)
        *(float2*)(outp + (size_t)row1 * 8 + tig * 2) =
            make_float2(fmaxf(o[2], 0.f), fmaxf(o[3], 0.f));
}

// ---------------------------------------------------------------------------
// Launcher (no allocation, graph-capturable)
// ---------------------------------------------------------------------------
extern "C" void kernel_launch(void* const* d_in, const int* in_sizes, int n_in,
                              void* d_out, int out_size) {
    const float* x    = (const float*)d_in[0];
    const void*  ei   = d_in[1];
    const float* s0Wl = (const float*)d_in[2];
    const float* s0bl = (const float*)d_in[3];
    const float* s0Wr = (const float*)d_in[4];
    const float* s1Wl = (const float*)d_in[5];
    const float* s1bl = (const float*)d_in[6];
    const float* s1Wr = (const float*)d_in[7];
    const float* l0W  = (const float*)d_in[8];
    const float* l0b  = (const float*)d_in[9];
    const float* l1W  = (const float*)d_in[10];
    const float* l1b  = (const float*)d_in[11];
    float* out = (float*)d_out;

    const int N = in_sizes[0] / D;
    const int E = in_sizes[1] / 2;
    const int NB = (N + SCAN_B - 1) / SCAN_B;

    cudaFuncSetAttribute(sage_mma<0, 0, 0>,
                         cudaFuncAttributeMaxDynamicSharedMemorySize, SM_BYTES);
    cudaFuncSetAttribute(sage_mma<1, 1, 1>,
                         cudaFuncAttributeMaxDynamicSharedMemorySize, SM_BYTES);

    // setup: zeroing + dtype sniff + all weight-plane precompute (one kernel)
    setup_kernel<<<(N + 255) / 256, 256>>>((const unsigned int*)ei, 2048, N,
                                           s0Wl, s0Wr, s1Wl, s1Wr, l0W, l1W);

    // CSR build: hist -> scan1(+offsets) -> scan3 -> fill
    hist_kernel<<<(E + 255) / 256, 256>>>(ei, E, N);
    scan1_kernel<<<NB, SCAN_B>>>(N, NB, E);
    scan3_kernel<<<NB, SCAN_B>>>(N);
    fill_kernel<<<(E + 255) / 256, 256>>>(ei, E, N);

    const int agg_blocks = (int)(((long long)N * 32 + 255) / 256);
    const int mma_blocks = (N + 127) / 128;

    // layer 0: agg(x) -> msum; sage -> g_h1
    agg_kernel<0><<<agg_blocks, 256>>>(x, N);
    sage_mma<0, 0, 0><<<mma_blocks, 256, SM_BYTES>>>(x, s0bl, nullptr, nullptr,
                                                     nullptr, N);

    // layer 1 + fused MLP head: agg(h1) -> msum; sage + head -> out
    agg_kernel<1><<<agg_blocks, 256>>>(x, N);
    sage_mma<1, 1, 1><<<mma_blocks, 256, SM_BYTES>>>(x, s1bl, l0b, l1b, out, N);
}